// round 2
// baseline (speedup 1.0000x reference)
#include <cuda_runtime.h>

#define BB 16
#define CC 64
#define HH 32
#define WW 32
#define TT 30
#define TP 32
#define HO 16
#define WO 16

// ---- scratch (static device memory; no allocations) ----
__device__ float g_c [BB*CC*HH*WW*TP];   // conv(u_t, W_in) for all t   (128 MiB)
__device__ float g_sf[BB*CC*HH*WW*TP];   // spikes s_a as float          (128 MiB)
__device__ float g_d [BB*CC*HO*WO*TP];   // conv(s_a, W_down, s2)        (32 MiB)
__device__ float g_za[BB*CC*HH*WW];
__device__ float g_zb[BB*CC*HO*WO];
__device__ float g_ubar[BB*CC*HH*WW];

// ============================================================
// conv1: c[t,b,co,h,w] = conv3x3 SAME (u[...,t], W_in), stride 1
// block: b, co-half (32 co), spatial tile 2x4; threads (tx=t lane 0..31, ty=0..7 -> 4 co each)
// ============================================================
__global__ __launch_bounds__(256) void conv1_k(const float* __restrict__ u,
                                               const float* __restrict__ Win)
{
    int tid = threadIdx.x;
    int tx = tid & 31;
    int ty = tid >> 5;
    int tile = blockIdx.x;            // 0..127
    int cg = blockIdx.y;              // 0..1
    int b  = blockIdx.z;              // 0..15
    int th = tile >> 3;               // 0..15, rows of 2
    int tw = tile & 7;                // 0..7,  cols of 4
    int h0 = th * 2, w0 = tw * 4;

    __shared__ float s_u[8][4][6][32];   // ci, row(h0-1..h0+2), col(w0-1..w0+4), t
    __shared__ float s_w[8][9][32];      // ci, tap, co

    float acc[4][8];
    #pragma unroll
    for (int j = 0; j < 4; j++)
        #pragma unroll
        for (int p = 0; p < 8; p++) acc[j][p] = 0.f;

    for (int cc = 0; cc < 8; cc++) {
        int ci0 = cc * 8;
        // load input tile (t lane = tx)
        for (int e = ty; e < 192; e += 8) {
            int ci = e / 24; int rem = e % 24;
            int r = rem / 6; int c = rem % 6;
            int gh = h0 - 1 + r;
            int gw = w0 - 1 + c;
            float v = 0.f;
            if (tx < TT && gh >= 0 && gh < HH && gw >= 0 && gw < WW)
                v = u[(((size_t)(b*CC + ci0+ci)*HH + gh)*WW + gw)*TT + tx];
            s_u[ci][r][c][tx] = v;
        }
        // load weights: W_in[co][ci][kh][kw] -> s_w[ci][tap][co_local]
        for (int e = tid; e < 8*9*32; e += 256) {
            int ci = e / 288; int rem = e % 288;
            int tap = rem / 32; int c = rem & 31;
            s_w[ci][tap][c] = Win[(cg*32 + c)*CC*9 + (ci0+ci)*9 + tap];
        }
        __syncthreads();
        #pragma unroll 4
        for (int ci = 0; ci < 8; ci++) {
            #pragma unroll
            for (int kh = 0; kh < 3; kh++) {
                #pragma unroll
                for (int kw = 0; kw < 3; kw++) {
                    float4 wv = *(const float4*)&s_w[ci][kh*3+kw][ty*4];
                    #pragma unroll
                    for (int pr = 0; pr < 2; pr++)
                        #pragma unroll
                        for (int pc = 0; pc < 4; pc++) {
                            float v = s_u[ci][pr+kh][pc+kw][tx];
                            int p = pr*4 + pc;
                            acc[0][p] += wv.x * v;
                            acc[1][p] += wv.y * v;
                            acc[2][p] += wv.z * v;
                            acc[3][p] += wv.w * v;
                        }
                }
            }
        }
        __syncthreads();
    }
    #pragma unroll
    for (int j = 0; j < 4; j++) {
        int co = cg*32 + ty*4 + j;
        #pragma unroll
        for (int pr = 0; pr < 2; pr++)
            #pragma unroll
            for (int pc = 0; pc < 4; pc++)
                g_c[(((size_t)(b*CC + co)*HH + h0+pr)*WW + (w0+pc))*TP + tx] = acc[j][pr*4+pc];
    }
}

// ============================================================
// scan A: per-pixel LIF over t on g_c; writes spikes (float, t padded w/ 0) + z_a
// ============================================================
__global__ __launch_bounds__(256) void scanA_k()
{
    int pix = blockIdx.x * blockDim.x + threadIdx.x;
    if (pix >= BB*CC*HH*WW) return;
    const float4* cp = (const float4*)&g_c[(size_t)pix * TP];
    float cr[32];
    #pragma unroll
    for (int i = 0; i < 8; i++) {
        float4 v = cp[i];
        cr[4*i+0] = v.x; cr[4*i+1] = v.y; cr[4*i+2] = v.z; cr[4*i+3] = v.w;
    }
    float out[32];
    float v = 0.f, cnt = 0.f;
    #pragma unroll
    for (int t = 0; t < TT; t++) {
        v = 0.5f * v + cr[t];
        float sp = (v >= 1.0f) ? 1.0f : 0.0f;
        v -= sp;
        cnt += sp;
        out[t] = sp;
    }
    out[30] = 0.f; out[31] = 0.f;
    float4* op = (float4*)&g_sf[(size_t)pix * TP];
    #pragma unroll
    for (int i = 0; i < 8; i++)
        op[i] = make_float4(out[4*i], out[4*i+1], out[4*i+2], out[4*i+3]);
    g_za[pix] = cnt * (1.0f / 30.0f);
}

// ============================================================
// conv2: d[t,b,co,ho,wo] = conv3x3 SAME stride2 (s_a_t, W_down)
// JAX SAME stride2: in = 2*out + k (pad_lo=0, pad_hi=1)
// ============================================================
__global__ __launch_bounds__(256) void conv2_k(const float* __restrict__ Wdn)
{
    int tid = threadIdx.x;
    int tx = tid & 31;
    int ty = tid >> 5;
    int tile = blockIdx.x;            // 0..31
    int cg = blockIdx.y;
    int b  = blockIdx.z;
    int th = tile >> 2;               // 0..7 rows of 2 (out)
    int tw = tile & 3;                // 0..3 cols of 4 (out)
    int h0 = th * 2, w0 = tw * 4;

    __shared__ float s_u[4][5][9][32];  // ci, in-row(2h0..2h0+4), in-col(2w0..2w0+8), t
    __shared__ float s_w[4][9][32];

    float acc[4][8];
    #pragma unroll
    for (int j = 0; j < 4; j++)
        #pragma unroll
        for (int p = 0; p < 8; p++) acc[j][p] = 0.f;

    for (int cc = 0; cc < 16; cc++) {
        int ci0 = cc * 4;
        for (int e = ty; e < 180; e += 8) {
            int ci = e / 45; int rem = e % 45;
            int r = rem / 9; int c = rem % 9;
            int gh = 2*h0 + r;
            int gw = 2*w0 + c;
            float v = 0.f;
            if (gh < HH && gw < WW)
                v = g_sf[(((size_t)(b*CC + ci0+ci)*HH + gh)*WW + gw)*TP + tx];
            s_u[ci][r][c][tx] = v;
        }
        for (int e = tid; e < 4*9*32; e += 256) {
            int ci = e / 288; int rem = e % 288;
            int tap = rem / 32; int c = rem & 31;
            s_w[ci][tap][c] = Wdn[(cg*32 + c)*CC*9 + (ci0+ci)*9 + tap];
        }
        __syncthreads();
        #pragma unroll
        for (int ci = 0; ci < 4; ci++) {
            #pragma unroll
            for (int kh = 0; kh < 3; kh++) {
                #pragma unroll
                for (int kw = 0; kw < 3; kw++) {
                    float4 wv = *(const float4*)&s_w[ci][kh*3+kw][ty*4];
                    #pragma unroll
                    for (int pr = 0; pr < 2; pr++)
                        #pragma unroll
                        for (int pc = 0; pc < 4; pc++) {
                            float v = s_u[ci][2*pr+kh][2*pc+kw][tx];
                            int p = pr*4 + pc;
                            acc[0][p] += wv.x * v;
                            acc[1][p] += wv.y * v;
                            acc[2][p] += wv.z * v;
                            acc[3][p] += wv.w * v;
                        }
                }
            }
        }
        __syncthreads();
    }
    #pragma unroll
    for (int j = 0; j < 4; j++) {
        int co = cg*32 + ty*4 + j;
        #pragma unroll
        for (int pr = 0; pr < 2; pr++)
            #pragma unroll
            for (int pc = 0; pc < 4; pc++)
                g_d[(((size_t)(b*CC + co)*HO + h0+pr)*WO + (w0+pc))*TP + tx] = acc[j][pr*4+pc];
    }
}

// ============================================================
// scan B: LIF over t on g_d; only z_b needed
// ============================================================
__global__ __launch_bounds__(256) void scanB_k()
{
    int pix = blockIdx.x * blockDim.x + threadIdx.x;
    if (pix >= BB*CC*HO*WO) return;
    const float4* cp = (const float4*)&g_d[(size_t)pix * TP];
    float cr[32];
    #pragma unroll
    for (int i = 0; i < 8; i++) {
        float4 v = cp[i];
        cr[4*i+0] = v.x; cr[4*i+1] = v.y; cr[4*i+2] = v.z; cr[4*i+3] = v.w;
    }
    float v = 0.f, cnt = 0.f;
    #pragma unroll
    for (int t = 0; t < TT; t++) {
        v = 0.5f * v + cr[t];
        float sp = (v >= 1.0f) ? 1.0f : 0.0f;
        v -= sp;
        cnt += sp;
    }
    g_zb[pix] = cnt * (1.0f / 30.0f);
}

// ============================================================
// u_bar: leaky temporal average (weights: t=29 -> 1+0.9^30, t=j<29 -> 0.9^(29-j); /norm)
// ============================================================
__global__ __launch_bounds__(256) void ubar_k(const float* __restrict__ u)
{
    int pix = blockIdx.x * blockDim.x + threadIdx.x;
    if (pix >= BB*CC*HH*WW) return;
    const float* up = u + (size_t)pix * TT;
    float p = 1.0f;
    #pragma unroll
    for (int i = 0; i < 30; i++) p *= 0.9f;      // 0.9^30
    float p31 = p * 0.9f;
    float inv = 0.1f / (1.0f - p31);
    float acc = (1.0f + p) * up[29];
    float w = 0.9f;
    #pragma unroll
    for (int j = 28; j >= 0; j--) {
        acc += w * up[j];
        w *= 0.9f;
    }
    g_ubar[pix] = acc * inv;
}

// ============================================================
// final A: a = clip(conv(u_bar,W_in) + conv(z_a,W_aa), 0, 1)   stride 1 SAME
// block: b, 16-co group, 8x8 spatial tile; threads: pix(64) x ty(4 -> 4 co)
// ============================================================
__global__ __launch_bounds__(256) void finalA_k(const float* __restrict__ Win,
                                                const float* __restrict__ Waa,
                                                float* __restrict__ outA)
{
    int tid = threadIdx.x;
    int pix = tid & 63;
    int ty  = tid >> 6;              // 0..3
    int pr = pix >> 3, pc = pix & 7;
    int tile = blockIdx.x;           // 0..15 (4x4)
    int cog  = blockIdx.y;           // 0..3
    int b    = blockIdx.z;
    int th = tile >> 2, tw = tile & 3;
    int h0 = th * 8, w0 = tw * 8;

    __shared__ float s_ub[8][10][10];
    __shared__ float s_za[8][10][10];
    __shared__ float s_w1[8][9][16];
    __shared__ float s_w2[8][9][16];

    float acc[4] = {0.f, 0.f, 0.f, 0.f};

    for (int cc = 0; cc < 8; cc++) {
        int ci0 = cc * 8;
        for (int e = tid; e < 800; e += 256) {
            int ci = e / 100; int rem = e % 100;
            int r = rem / 10; int c = rem % 10;
            int gh = h0 - 1 + r;
            int gw = w0 - 1 + c;
            bool ok = (gh >= 0 && gh < HH && gw >= 0 && gw < WW);
            int gi = ((b*CC + ci0+ci)*HH + gh)*WW + gw;
            s_ub[ci][r][c] = ok ? g_ubar[gi] : 0.f;
            s_za[ci][r][c] = ok ? g_za[gi]   : 0.f;
        }
        for (int e = tid; e < 8*9*16; e += 256) {
            int ci = e / 144; int rem = e % 144;
            int tap = rem / 16; int c = rem & 15;
            int wi = (cog*16 + c)*CC*9 + (ci0+ci)*9 + tap;
            s_w1[ci][tap][c] = Win[wi];
            s_w2[ci][tap][c] = Waa[wi];
        }
        __syncthreads();
        #pragma unroll 2
        for (int ci = 0; ci < 8; ci++) {
            #pragma unroll
            for (int kh = 0; kh < 3; kh++) {
                #pragma unroll
                for (int kw = 0; kw < 3; kw++) {
                    float vu = s_ub[ci][pr+kh][pc+kw];
                    float vz = s_za[ci][pr+kh][pc+kw];
                    float4 w1 = *(const float4*)&s_w1[ci][kh*3+kw][ty*4];
                    float4 w2 = *(const float4*)&s_w2[ci][kh*3+kw][ty*4];
                    acc[0] += w1.x*vu + w2.x*vz;
                    acc[1] += w1.y*vu + w2.y*vz;
                    acc[2] += w1.z*vu + w2.z*vz;
                    acc[3] += w1.w*vu + w2.w*vz;
                }
            }
        }
        __syncthreads();
    }
    #pragma unroll
    for (int j = 0; j < 4; j++) {
        int co = cog*16 + ty*4 + j;
        float val = acc[j];
        val = fminf(fmaxf(val, 0.f), 1.f);
        outA[((b*CC + co)*HH + h0+pr)*WW + (w0+pc)] = val;
    }
}

// ============================================================
// final B: b_out = clip(conv(a,W_down,s2) + conv(z_b,W_bb,s1), 0, 1)  on 16x16
// ============================================================
__global__ __launch_bounds__(256) void finalB_k(const float* __restrict__ Wdn,
                                                const float* __restrict__ Wbb,
                                                const float* __restrict__ aIn,
                                                float* __restrict__ outB)
{
    int tid = threadIdx.x;
    int pix = tid & 63;
    int ty  = tid >> 6;
    int pr = pix >> 3, pc = pix & 7;
    int tile = blockIdx.x;           // 0..3 (2x2)
    int cog  = blockIdx.y;           // 0..3
    int b    = blockIdx.z;
    int th = tile >> 1, tw = tile & 1;
    int h0 = th * 8, w0 = tw * 8;    // output coords (16x16)

    __shared__ float s_a[8][17][17];
    __shared__ float s_z[8][10][10];
    __shared__ float s_w1[8][9][16];
    __shared__ float s_w2[8][9][16];

    float acc[4] = {0.f, 0.f, 0.f, 0.f};

    for (int cc = 0; cc < 8; cc++) {
        int ci0 = cc * 8;
        for (int e = tid; e < 8*289; e += 256) {
            int ci = e / 289; int rem = e % 289;
            int r = rem / 17; int c = rem % 17;
            int gh = 2*h0 + r;     // stride-2 SAME: in = 2*out + k, pad_hi only
            int gw = 2*w0 + c;
            float v = 0.f;
            if (gh < HH && gw < WW)
                v = aIn[((b*CC + ci0+ci)*HH + gh)*WW + gw];
            s_a[ci][r][c] = v;
        }
        for (int e = tid; e < 800; e += 256) {
            int ci = e / 100; int rem = e % 100;
            int r = rem / 10; int c = rem % 10;
            int gh = h0 - 1 + r;
            int gw = w0 - 1 + c;
            bool ok = (gh >= 0 && gh < HO && gw >= 0 && gw < WO);
            s_z[ci][r][c] = ok ? g_zb[((b*CC + ci0+ci)*HO + gh)*WO + gw] : 0.f;
        }
        for (int e = tid; e < 8*9*16; e += 256) {
            int ci = e / 144; int rem = e % 144;
            int tap = rem / 16; int c = rem & 15;
            int wi = (cog*16 + c)*CC*9 + (ci0+ci)*9 + tap;
            s_w1[ci][tap][c] = Wdn[wi];
            s_w2[ci][tap][c] = Wbb[wi];
        }
        __syncthreads();
        #pragma unroll 2
        for (int ci = 0; ci < 8; ci++) {
            #pragma unroll
            for (int kh = 0; kh < 3; kh++) {
                #pragma unroll
                for (int kw = 0; kw < 3; kw++) {
                    float va = s_a[ci][2*pr+kh][2*pc+kw];
                    float vz = s_z[ci][pr+kh][pc+kw];
                    float4 w1 = *(const float4*)&s_w1[ci][kh*3+kw][ty*4];
                    float4 w2 = *(const float4*)&s_w2[ci][kh*3+kw][ty*4];
                    acc[0] += w1.x*va + w2.x*vz;
                    acc[1] += w1.y*va + w2.y*vz;
                    acc[2] += w1.z*va + w2.z*vz;
                    acc[3] += w1.w*va + w2.w*vz;
                }
            }
        }
        __syncthreads();
    }
    #pragma unroll
    for (int j = 0; j < 4; j++) {
        int co = cog*16 + ty*4 + j;
        float val = acc[j];
        val = fminf(fmaxf(val, 0.f), 1.f);
        outB[((b*CC + co)*HO + h0+pr)*WO + (w0+pc)] = val;
    }
}

// ============================================================
extern "C" void kernel_launch(void* const* d_in, const int* in_sizes, int n_in,
                              void* d_out, int out_size)
{
    (void)in_sizes; (void)n_in; (void)out_size;
    const float* u   = (const float*)d_in[0];
    const float* Win = (const float*)d_in[1];
    const float* Waa = (const float*)d_in[2];
    const float* Wdn = (const float*)d_in[3];
    const float* Wbb = (const float*)d_in[4];
    float* outA = (float*)d_out;                      // a: [16,64,32,32]
    float* outB = outA + BB*CC*HH*WW;                 // b: [16,64,16,16]

    ubar_k <<<(BB*CC*HH*WW + 255)/256, 256>>>(u);
    conv1_k<<<dim3(128, 2, BB), 256>>>(u, Win);
    scanA_k<<<(BB*CC*HH*WW + 255)/256, 256>>>();
    conv2_k<<<dim3(32, 2, BB), 256>>>(Wdn);
    scanB_k<<<(BB*CC*HO*WO + 255)/256, 256>>>();
    finalA_k<<<dim3(16, 4, BB), 256>>>(Win, Waa, outA);
    finalB_k<<<dim3(4, 4, BB), 256>>>(Wdn, Wbb, outA, outB);
}

// round 4
// speedup vs baseline: 1.3615x; 1.3615x over previous
#include <cuda_runtime.h>

#define BB 16
#define CC 64
#define HH 32
#define WW 32
#define TT 30
#define TP 32
#define HO 16
#define WO 16

// ---- scratch (static device memory; no allocations) ----
__device__ float g_sf[BB*CC*HH*WW*TP];   // spikes s_a as float (t padded to 32)
__device__ float g_za[BB*CC*HH*WW];
__device__ float g_zb[BB*CC*HO*WO];
__device__ float g_ubar[BB*CC*HH*WW];

// packed f32x2 helpers
static __device__ __forceinline__ unsigned long long pk2(float x) {
    unsigned long long r;
    asm("mov.b64 %0, {%1, %1};" : "=l"(r) : "f"(x));
    return r;
}
static __device__ __forceinline__ unsigned long long fma2(unsigned long long a,
                                                          unsigned long long b,
                                                          unsigned long long c) {
    unsigned long long d;
    asm("fma.rn.f32x2 %0, %1, %2, %3;" : "=l"(d) : "l"(a), "l"(b), "l"(c));
    return d;
}
static __device__ __forceinline__ void unpk2(unsigned long long v, float& lo, float& hi) {
    asm("mov.b64 {%0, %1}, %2;" : "=f"(lo), "=f"(hi) : "l"(v));
}

// ============================================================
// conv1 + LIF scan A fused.
// block: b(z), co-half cg(y), spatial tile (x: 16x8 tiles of 2x4 pixels)
// threads: tx = t lane (0..31), ty = co-quad (0..7)
// accumulators packed f32x2 along co (2 co per b64).
// ============================================================
__global__ __launch_bounds__(256) void conv1_k(const float* __restrict__ u,
                                               const float* __restrict__ Win)
{
    __shared__ float sm[8448];           // s_u 6144 | s_w 2304 ; reused as 256x33 transpose
    int tid = threadIdx.x;
    int tx = tid & 31;
    int ty = tid >> 5;
    int tile = blockIdx.x;            // 0..127
    int cg = blockIdx.y;              // 0..1
    int b  = blockIdx.z;              // 0..15
    int h0 = (tile >> 3) * 2;
    int w0 = (tile & 7) * 4;

    float* s_u = sm;                  // [ci][r 4][c 6][t 32]
    float* s_w = sm + 6144;           // [ci][tap 9][co 32]

    unsigned long long acc[2][8];
    #pragma unroll
    for (int j = 0; j < 2; j++)
        #pragma unroll
        for (int p = 0; p < 8; p++) acc[j][p] = 0ull;

    // hoisted load bases (ci = ty for input tile, co = tx for weights)
    const float* ubase = u + ((size_t)(b*CC + ty)*HH) * (WW*TT);   // + ci0*HH*WW*TT later
    const float* wbase = Win + (cg*32 + tx)*CC*9 + ty*9;            // + ci0*9 later
    bool tok = (tx < TT);

    for (int cc = 0; cc < 8; cc++) {
        int ci0 = cc * 8;
        // ---- input tile: thread loads ci=ty, rows 0..3, cols 0..5 ----
        const float* up = ubase + (size_t)ci0 * HH*WW*TT;
        #pragma unroll
        for (int r = 0; r < 4; r++) {
            int gh = h0 - 1 + r;
            bool hok = (gh >= 0) & (gh < HH);
            #pragma unroll
            for (int c = 0; c < 6; c++) {
                int gw = w0 - 1 + c;
                bool ok = tok & hok & (gw >= 0) & (gw < WW);
                float v = ok ? up[((size_t)gh*WW + gw)*TT + tx] : 0.f;
                sm[ty*768 + r*192 + c*32 + tx] = v;
            }
        }
        // ---- weights: thread loads ci=ty, taps 0..8, co=tx ----
        const float* wp = wbase + ci0*9;
        #pragma unroll
        for (int k = 0; k < 9; k++)
            s_w[ty*288 + k*32 + tx] = wp[k];
        __syncthreads();

        #pragma unroll 4
        for (int ci = 0; ci < 8; ci++) {
            const float* su = s_u + ci*768;
            const float* swc = s_w + ci*288 + (ty<<2);
            #pragma unroll
            for (int rr = 0; rr < 4; rr++) {
                unsigned long long vd[6];
                #pragma unroll
                for (int c = 0; c < 6; c++)
                    vd[c] = pk2(su[rr*192 + c*32 + tx]);
                #pragma unroll
                for (int kh = 0; kh < 3; kh++) {
                    int pr = rr - kh;
                    if (pr == 0 || pr == 1) {
                        #pragma unroll
                        for (int kw = 0; kw < 3; kw++) {
                            ulonglong2 wv = *(const ulonglong2*)(swc + (kh*3+kw)*32);
                            #pragma unroll
                            for (int pc = 0; pc < 4; pc++) {
                                int p = pr*4 + pc;
                                acc[0][p] = fma2(wv.x, vd[pc+kw], acc[0][p]);
                                acc[1][p] = fma2(wv.y, vd[pc+kw], acc[1][p]);
                            }
                        }
                    }
                }
            }
        }
        __syncthreads();
    }

    // ---- transpose into [copix][t] (pitch 33) ----
    #pragma unroll
    for (int j = 0; j < 2; j++)
        #pragma unroll
        for (int p = 0; p < 8; p++) {
            float lo, hi;
            unpk2(acc[j][p], lo, hi);
            sm[((ty*4 + 2*j    )*8 + p)*33 + tx] = lo;
            sm[((ty*4 + 2*j + 1)*8 + p)*33 + tx] = hi;
        }
    __syncthreads();

    // ---- LIF scan: thread tid owns (co_local = tid>>3, pix = tid&7) ----
    {
        int co_local = tid >> 3;
        int p = tid & 7;
        int h = h0 + (p >> 2);
        int w = w0 + (p & 3);
        int co = cg*32 + co_local;
        size_t pixIdx = ((size_t)(b*CC + co)*HH + h)*WW + w;

        float out[32];
        float v = 0.f, cnt = 0.f;
        #pragma unroll
        for (int t = 0; t < TT; t++) {
            v = 0.5f * v + sm[tid*33 + t];
            float sp = (v >= 1.0f) ? 1.0f : 0.0f;
            v -= sp;
            cnt += sp;
            out[t] = sp;
        }
        out[30] = 0.f; out[31] = 0.f;
        float4* op = (float4*)&g_sf[pixIdx * TP];
        #pragma unroll
        for (int i = 0; i < 8; i++)
            op[i] = make_float4(out[4*i], out[4*i+1], out[4*i+2], out[4*i+3]);
        g_za[pixIdx] = cnt * (1.0f / 30.0f);
    }
}

// ============================================================
// conv2 (stride-2 SAME: in = 2*out + k) + LIF scan B fused.
// block: b(z), cg(y), 8x4 tiles of 2x4 out-pixels (x)
// ============================================================
__global__ __launch_bounds__(256) void conv2_k(const float* __restrict__ Wdn)
{
    __shared__ float sm[8448];           // s_u 5760 | s_w 1152 ; reused as transpose
    int tid = threadIdx.x;
    int tx = tid & 31;
    int ty = tid >> 5;
    int tile = blockIdx.x;            // 0..31
    int cg = blockIdx.y;
    int b  = blockIdx.z;
    int h0 = (tile >> 2) * 2;         // out coords
    int w0 = (tile & 3) * 4;

    float* s_u = sm;                  // [ci 4][r 5][c 9][t 32]
    float* s_w = sm + 5760;           // [ci 4][tap 9][co 32]

    unsigned long long acc[2][8];
    #pragma unroll
    for (int j = 0; j < 2; j++)
        #pragma unroll
        for (int p = 0; p < 8; p++) acc[j][p] = 0ull;

    int lci = ty & 3;                 // this thread's load ci
    int rg  = ty >> 2;                // row group: 0 -> rows 0..2, 1 -> rows 3..4

    const float* sfbase = g_sf + ((size_t)(b*CC + lci)*HH) * (WW*TP);
    const float* wbase  = Wdn + (cg*32 + tx)*CC*9 + lci*9;

    for (int cc = 0; cc < 16; cc++) {
        int ci0 = cc * 4;
        // ---- input tile (spikes), rows split between ty>>2 groups ----
        const float* up = sfbase + (size_t)ci0 * HH*WW*TP;
        #pragma unroll
        for (int rs = 0; rs < 3; rs++) {
            int r = rg*3 + rs;
            if (r < 5) {
                int gh = 2*h0 + r;
                bool hok = (gh < HH);
                #pragma unroll
                for (int c = 0; c < 9; c++) {
                    int gw = 2*w0 + c;
                    bool ok = hok & (gw < WW);
                    float v = ok ? up[((size_t)gh*WW + gw)*TP + tx] : 0.f;
                    s_u[lci*1440 + r*288 + c*32 + tx] = v;
                }
            }
        }
        // ---- weights: ci=lci, taps split by rg, co=tx ----
        const float* wp = wbase + ci0*9;
        #pragma unroll
        for (int k = 0; k < 5; k++) {
            int tap = rg*5 + k;
            if (tap < 9)
                s_w[lci*288 + tap*32 + tx] = wp[tap];
        }
        __syncthreads();

        #pragma unroll
        for (int ci = 0; ci < 4; ci++) {
            const float* su = s_u + ci*1440;
            const float* swc = s_w + ci*288 + (ty<<2);
            #pragma unroll
            for (int rr = 0; rr < 5; rr++) {
                unsigned long long vd[9];
                #pragma unroll
                for (int c = 0; c < 9; c++)
                    vd[c] = pk2(su[rr*288 + c*32 + tx]);
                #pragma unroll
                for (int kh = 0; kh < 3; kh++) {
                    int pr2 = rr - kh;            // = 2*pr
                    if (pr2 == 0 || pr2 == 2) {
                        int pr = pr2 >> 1;
                        #pragma unroll
                        for (int kw = 0; kw < 3; kw++) {
                            ulonglong2 wv = *(const ulonglong2*)(swc + (kh*3+kw)*32);
                            #pragma unroll
                            for (int pc = 0; pc < 4; pc++) {
                                int p = pr*4 + pc;
                                acc[0][p] = fma2(wv.x, vd[2*pc+kw], acc[0][p]);
                                acc[1][p] = fma2(wv.y, vd[2*pc+kw], acc[1][p]);
                            }
                        }
                    }
                }
            }
        }
        __syncthreads();
    }

    // ---- transpose + scan B (only z_b) ----
    #pragma unroll
    for (int j = 0; j < 2; j++)
        #pragma unroll
        for (int p = 0; p < 8; p++) {
            float lo, hi;
            unpk2(acc[j][p], lo, hi);
            sm[((ty*4 + 2*j    )*8 + p)*33 + tx] = lo;
            sm[((ty*4 + 2*j + 1)*8 + p)*33 + tx] = hi;
        }
    __syncthreads();
    {
        int co_local = tid >> 3;
        int p = tid & 7;
        int h = h0 + (p >> 2);
        int w = w0 + (p & 3);
        int co = cg*32 + co_local;
        float v = 0.f, cnt = 0.f;
        #pragma unroll
        for (int t = 0; t < TT; t++) {
            v = 0.5f * v + sm[tid*33 + t];
            float sp = (v >= 1.0f) ? 1.0f : 0.0f;
            v -= sp;
            cnt += sp;
        }
        g_zb[((size_t)(b*CC + co)*HO + h)*WO + w] = cnt * (1.0f / 30.0f);
    }
}

// ============================================================
// u_bar: leaky temporal average
// ============================================================
__global__ __launch_bounds__(256) void ubar_k(const float* __restrict__ u)
{
    int pix = blockIdx.x * blockDim.x + threadIdx.x;
    if (pix >= BB*CC*HH*WW) return;
    const float* up = u + (size_t)pix * TT;
    float p = 1.0f;
    #pragma unroll
    for (int i = 0; i < 30; i++) p *= 0.9f;      // 0.9^30
    float p31 = p * 0.9f;
    float inv = 0.1f / (1.0f - p31);
    float acc = (1.0f + p) * up[29];
    float w = 0.9f;
    #pragma unroll
    for (int j = 28; j >= 0; j--) {
        acc += w * up[j];
        w *= 0.9f;
    }
    g_ubar[pix] = acc * inv;
}

// ============================================================
// final A: a = clip(conv(u_bar,W_in) + conv(z_a,W_aa), 0, 1)
// ============================================================
__global__ __launch_bounds__(256) void finalA_k(const float* __restrict__ Win,
                                                const float* __restrict__ Waa,
                                                float* __restrict__ outA)
{
    int tid = threadIdx.x;
    int pix = tid & 63;
    int ty  = tid >> 6;              // 0..3
    int pr = pix >> 3, pc = pix & 7;
    int tile = blockIdx.x;           // 0..15 (4x4)
    int cog  = blockIdx.y;           // 0..3
    int b    = blockIdx.z;
    int h0 = (tile >> 2) * 8, w0 = (tile & 3) * 8;

    __shared__ float s_ub[8][10][10];
    __shared__ float s_za[8][10][10];
    __shared__ float s_w1[8][9][16];
    __shared__ float s_w2[8][9][16];

    float acc[4] = {0.f, 0.f, 0.f, 0.f};

    for (int cc = 0; cc < 8; cc++) {
        int ci0 = cc * 8;
        for (int e = tid; e < 800; e += 256) {
            int ci = e / 100; int rem = e % 100;
            int r = rem / 10; int c = rem % 10;
            int gh = h0 - 1 + r;
            int gw = w0 - 1 + c;
            bool ok = (gh >= 0 && gh < HH && gw >= 0 && gw < WW);
            int gi = ((b*CC + ci0+ci)*HH + gh)*WW + gw;
            s_ub[ci][r][c] = ok ? g_ubar[gi] : 0.f;
            s_za[ci][r][c] = ok ? g_za[gi]   : 0.f;
        }
        for (int e = tid; e < 8*9*16; e += 256) {
            int ci = e / 144; int rem = e % 144;
            int tap = rem / 16; int c = rem & 15;
            int wi = (cog*16 + c)*CC*9 + (ci0+ci)*9 + tap;
            s_w1[ci][tap][c] = Win[wi];
            s_w2[ci][tap][c] = Waa[wi];
        }
        __syncthreads();
        #pragma unroll 2
        for (int ci = 0; ci < 8; ci++) {
            #pragma unroll
            for (int kh = 0; kh < 3; kh++) {
                #pragma unroll
                for (int kw = 0; kw < 3; kw++) {
                    float vu = s_ub[ci][pr+kh][pc+kw];
                    float vz = s_za[ci][pr+kh][pc+kw];
                    float4 w1 = *(const float4*)&s_w1[ci][kh*3+kw][ty*4];
                    float4 w2 = *(const float4*)&s_w2[ci][kh*3+kw][ty*4];
                    acc[0] += w1.x*vu + w2.x*vz;
                    acc[1] += w1.y*vu + w2.y*vz;
                    acc[2] += w1.z*vu + w2.z*vz;
                    acc[3] += w1.w*vu + w2.w*vz;
                }
            }
        }
        __syncthreads();
    }
    #pragma unroll
    for (int j = 0; j < 4; j++) {
        int co = cog*16 + ty*4 + j;
        float val = fminf(fmaxf(acc[j], 0.f), 1.f);
        outA[((b*CC + co)*HH + h0+pr)*WW + (w0+pc)] = val;
    }
}

// ============================================================
// final B: b_out = clip(conv(a,W_down,s2) + conv(z_b,W_bb), 0, 1) on 16x16
// ============================================================
__global__ __launch_bounds__(256) void finalB_k(const float* __restrict__ Wdn,
                                                const float* __restrict__ Wbb,
                                                const float* __restrict__ aIn,
                                                float* __restrict__ outB)
{
    int tid = threadIdx.x;
    int pix = tid & 63;
    int ty  = tid >> 6;
    int pr = pix >> 3, pc = pix & 7;
    int tile = blockIdx.x;           // 0..3 (2x2)
    int cog  = blockIdx.y;           // 0..3
    int b    = blockIdx.z;
    int h0 = (tile >> 1) * 8, w0 = (tile & 1) * 8;   // output coords

    __shared__ float s_a[8][17][17];
    __shared__ float s_z[8][10][10];
    __shared__ float s_w1[8][9][16];
    __shared__ float s_w2[8][9][16];

    float acc[4] = {0.f, 0.f, 0.f, 0.f};

    for (int cc = 0; cc < 8; cc++) {
        int ci0 = cc * 8;
        for (int e = tid; e < 8*289; e += 256) {
            int ci = e / 289; int rem = e % 289;
            int r = rem / 17; int c = rem % 17;
            int gh = 2*h0 + r;       // stride-2 SAME: pad_hi only
            int gw = 2*w0 + c;
            float v = 0.f;
            if (gh < HH && gw < WW)
                v = aIn[((b*CC + ci0+ci)*HH + gh)*WW + gw];
            s_a[ci][r][c] = v;
        }
        for (int e = tid; e < 800; e += 256) {
            int ci = e / 100; int rem = e % 100;
            int r = rem / 10; int c = rem % 10;
            int gh = h0 - 1 + r;
            int gw = w0 - 1 + c;
            bool ok = (gh >= 0 && gh < HO && gw >= 0 && gw < WO);
            s_z[ci][r][c] = ok ? g_zb[((b*CC + ci0+ci)*HO + gh)*WO + gw] : 0.f;
        }
        for (int e = tid; e < 8*9*16; e += 256) {
            int ci = e / 144; int rem = e % 144;
            int tap = rem / 16; int c = rem & 15;
            int wi = (cog*16 + c)*CC*9 + (ci0+ci)*9 + tap;
            s_w1[ci][tap][c] = Wdn[wi];
            s_w2[ci][tap][c] = Wbb[wi];
        }
        __syncthreads();
        #pragma unroll 2
        for (int ci = 0; ci < 8; ci++) {
            #pragma unroll
            for (int kh = 0; kh < 3; kh++) {
                #pragma unroll
                for (int kw = 0; kw < 3; kw++) {
                    float va = s_a[ci][2*pr+kh][2*pc+kw];
                    float vz = s_z[ci][pr+kh][pc+kw];
                    float4 w1 = *(const float4*)&s_w1[ci][kh*3+kw][ty*4];
                    float4 w2 = *(const float4*)&s_w2[ci][kh*3+kw][ty*4];
                    acc[0] += w1.x*va + w2.x*vz;
                    acc[1] += w1.y*va + w2.y*vz;
                    acc[2] += w1.z*va + w2.z*vz;
                    acc[3] += w1.w*va + w2.w*vz;
                }
            }
        }
        __syncthreads();
    }
    #pragma unroll
    for (int j = 0; j < 4; j++) {
        int co = cog*16 + ty*4 + j;
        float val = fminf(fmaxf(acc[j], 0.f), 1.f);
        outB[((b*CC + co)*HO + h0+pr)*WO + (w0+pc)] = val;
    }
}

// ============================================================
extern "C" void kernel_launch(void* const* d_in, const int* in_sizes, int n_in,
                              void* d_out, int out_size)
{
    (void)in_sizes; (void)n_in; (void)out_size;
    const float* u   = (const float*)d_in[0];
    const float* Win = (const float*)d_in[1];
    const float* Waa = (const float*)d_in[2];
    const float* Wdn = (const float*)d_in[3];
    const float* Wbb = (const float*)d_in[4];
    float* outA = (float*)d_out;                      // a: [16,64,32,32]
    float* outB = outA + BB*CC*HH*WW;                 // b: [16,64,16,16]

    ubar_k <<<(BB*CC*HH*WW + 255)/256, 256>>>(u);
    conv1_k<<<dim3(128, 2, BB), 256>>>(u, Win);
    conv2_k<<<dim3(32, 2, BB), 256>>>(Wdn);
    finalA_k<<<dim3(16, 4, BB), 256>>>(Win, Waa, outA);
    finalB_k<<<dim3(4, 4, BB), 256>>>(Wdn, Wbb, outA, outB);
}

// round 5
// speedup vs baseline: 1.5024x; 1.1035x over previous
#include <cuda_runtime.h>

#define BB 16
#define CC 64
#define HH 32
#define WW 32
#define TT 30
#define TP 32
#define HO 16
#define WO 16

// ---- scratch (static device memory; no allocations) ----
__device__ float g_sf[BB*CC*HH*WW*TP];   // spikes s_a as float (t padded to 32)
__device__ float g_za[BB*CC*HH*WW];
__device__ float g_zb[BB*CC*HO*WO];
__device__ float g_ubar[BB*CC*HH*WW];

// packed f32x2 helpers
static __device__ __forceinline__ unsigned long long pk2(float x) {
    unsigned long long r;
    asm("mov.b64 %0, {%1, %1};" : "=l"(r) : "f"(x));
    return r;
}
static __device__ __forceinline__ unsigned long long fma2(unsigned long long a,
                                                          unsigned long long b,
                                                          unsigned long long c) {
    unsigned long long d;
    asm("fma.rn.f32x2 %0, %1, %2, %3;" : "=l"(d) : "l"(a), "l"(b), "l"(c));
    return d;
}
static __device__ __forceinline__ void unpk2(unsigned long long v, float& lo, float& hi) {
    asm("mov.b64 {%0, %1}, %2;" : "=f"(lo), "=f"(hi) : "l"(v));
}

// ============================================================
// conv1 + LIF scan A fused. Dynamic smem 98304 B:
//   s_w[64ci][9tap][32co] = 18432 floats   (aliased by 256x33 transpose later)
//   s_u[8ci][4r][6c][32t] =  6144 floats
// threads: tx = t lane, ty = ci_l (loads) / co-quad (compute)
// ============================================================
__global__ __launch_bounds__(256) void conv1_k(const float* __restrict__ u,
                                               const float* __restrict__ Win)
{
    extern __shared__ float sm[];
    float* s_w = sm;             // 18432 floats
    float* s_u = sm + 18432;     // 6144 floats

    int tid = threadIdx.x;
    int tx = tid & 31;
    int ty = tid >> 5;
    int tile = blockIdx.x;            // 0..127
    int cg = blockIdx.y;              // 0..1
    int b  = blockIdx.z;              // 0..15
    int h0 = (tile >> 3) * 2;
    int w0 = (tile & 7) * 4;

    // ---- full weight preload: s_w[(ci*9+tap)*32 + co] ----
    {
        const float* wsrc = Win + (size_t)cg * 32 * 576;
        for (int e = tid; e < 4608; e += 256) {
            int co = e & 31;
            int r  = e >> 5;                  // 0..143 float4 rows
            float4 v = ((const float4*)(wsrc + (size_t)co * 576))[r];
            int i0 = r * 4;
            s_w[(i0+0)*32 + co] = v.x;
            s_w[(i0+1)*32 + co] = v.y;
            s_w[(i0+2)*32 + co] = v.z;
            s_w[(i0+3)*32 + co] = v.w;
        }
    }

    unsigned long long acc[2][8];
    #pragma unroll
    for (int j = 0; j < 2; j++)
        #pragma unroll
        for (int p = 0; p < 8; p++) acc[j][p] = 0ull;

    const float* ubase = u + (size_t)(b*CC + ty) * HH*WW*TT;
    bool tok = (tx < TT);
    float pf[24];

    auto load_cc = [&](int cc) {
        const float* up = ubase + (size_t)cc * 8 * HH*WW*TT;
        #pragma unroll
        for (int r = 0; r < 4; r++) {
            int gh = h0 - 1 + r;
            bool hok = (gh >= 0) & (gh < HH);
            #pragma unroll
            for (int c = 0; c < 6; c++) {
                int gw = w0 - 1 + c;
                bool ok = tok & hok & (gw >= 0) & (gw < WW);
                pf[r*6+c] = ok ? up[((size_t)gh*WW + gw)*TT + tx] : 0.f;
            }
        }
    };

    load_cc(0);
    __syncthreads();      // weights visible

    for (int cc = 0; cc < 8; cc++) {
        #pragma unroll
        for (int r = 0; r < 4; r++)
            #pragma unroll
            for (int c = 0; c < 6; c++)
                s_u[ty*768 + r*192 + c*32 + tx] = pf[r*6+c];
        __syncthreads();
        if (cc < 7) load_cc(cc + 1);     // LDGs overlap compute

        #pragma unroll 4
        for (int ci = 0; ci < 8; ci++) {
            const float* su  = s_u + ci*768;
            const float* swc = s_w + (cc*8 + ci)*288 + (ty<<2);
            #pragma unroll
            for (int rr = 0; rr < 4; rr++) {
                unsigned long long vd[6];
                #pragma unroll
                for (int c = 0; c < 6; c++)
                    vd[c] = pk2(su[rr*192 + c*32 + tx]);
                #pragma unroll
                for (int kh = 0; kh < 3; kh++) {
                    int pr = rr - kh;
                    if (pr == 0 || pr == 1) {
                        #pragma unroll
                        for (int kw = 0; kw < 3; kw++) {
                            ulonglong2 wv = *(const ulonglong2*)(swc + (kh*3+kw)*32);
                            #pragma unroll
                            for (int pc = 0; pc < 4; pc++) {
                                int p = pr*4 + pc;
                                acc[0][p] = fma2(wv.x, vd[pc+kw], acc[0][p]);
                                acc[1][p] = fma2(wv.y, vd[pc+kw], acc[1][p]);
                            }
                        }
                    }
                }
            }
        }
        __syncthreads();
    }

    // ---- transpose into [copix][t] pitch 33 (aliases s_w region) ----
    #pragma unroll
    for (int j = 0; j < 2; j++)
        #pragma unroll
        for (int p = 0; p < 8; p++) {
            float lo, hi;
            unpk2(acc[j][p], lo, hi);
            sm[((ty*4 + 2*j    )*8 + p)*33 + tx] = lo;
            sm[((ty*4 + 2*j + 1)*8 + p)*33 + tx] = hi;
        }
    __syncthreads();

    {
        int co_local = tid >> 3;
        int p = tid & 7;
        int h = h0 + (p >> 2);
        int w = w0 + (p & 3);
        int co = cg*32 + co_local;
        size_t pixIdx = ((size_t)(b*CC + co)*HH + h)*WW + w;

        float out[32];
        float v = 0.f, cnt = 0.f;
        #pragma unroll
        for (int t = 0; t < TT; t++) {
            v = 0.5f * v + sm[tid*33 + t];
            float sp = (v >= 1.0f) ? 1.0f : 0.0f;
            v -= sp;
            cnt += sp;
            out[t] = sp;
        }
        out[30] = 0.f; out[31] = 0.f;
        float4* op = (float4*)&g_sf[pixIdx * TP];
        #pragma unroll
        for (int i = 0; i < 8; i++)
            op[i] = make_float4(out[4*i], out[4*i+1], out[4*i+2], out[4*i+3]);
        g_za[pixIdx] = cnt * (1.0f / 30.0f);
    }
}

// ============================================================
// conv2 (stride-2 SAME: in = 2*out + k) + LIF scan B fused.
// Dynamic smem 96768 B: s_w 18432 floats | s_u[4][5][9][32] 5760 floats
// ============================================================
__global__ __launch_bounds__(256) void conv2_k(const float* __restrict__ Wdn)
{
    extern __shared__ float sm[];
    float* s_w = sm;
    float* s_u = sm + 18432;

    int tid = threadIdx.x;
    int tx = tid & 31;
    int ty = tid >> 5;
    int tile = blockIdx.x;            // 0..31
    int cg = blockIdx.y;
    int b  = blockIdx.z;
    int h0 = (tile >> 2) * 2;         // out coords
    int w0 = (tile & 3) * 4;

    // ---- full weight preload ----
    {
        const float* wsrc = Wdn + (size_t)cg * 32 * 576;
        for (int e = tid; e < 4608; e += 256) {
            int co = e & 31;
            int r  = e >> 5;
            float4 v = ((const float4*)(wsrc + (size_t)co * 576))[r];
            int i0 = r * 4;
            s_w[(i0+0)*32 + co] = v.x;
            s_w[(i0+1)*32 + co] = v.y;
            s_w[(i0+2)*32 + co] = v.z;
            s_w[(i0+3)*32 + co] = v.w;
        }
    }

    unsigned long long acc[2][8];
    #pragma unroll
    for (int j = 0; j < 2; j++)
        #pragma unroll
        for (int p = 0; p < 8; p++) acc[j][p] = 0ull;

    int lci = ty & 3;
    int rg  = ty >> 2;                // 0 -> rows 0..2, 1 -> rows 3..4
    const float* sfbase = g_sf + (size_t)(b*CC + lci) * HH*WW*TP;
    float pf[27];

    auto load_cc = [&](int cc) {
        const float* up = sfbase + (size_t)cc * 4 * HH*WW*TP;
        #pragma unroll
        for (int rs = 0; rs < 3; rs++) {
            int r = rg*3 + rs;
            if (r < 5) {
                int gh = 2*h0 + r;
                bool hok = (gh < HH);
                #pragma unroll
                for (int c = 0; c < 9; c++) {
                    int gw = 2*w0 + c;
                    bool ok = hok & (gw < WW);
                    pf[rs*9+c] = ok ? up[((size_t)gh*WW + gw)*TP + tx] : 0.f;
                }
            }
        }
    };

    load_cc(0);
    __syncthreads();

    for (int cc = 0; cc < 16; cc++) {
        #pragma unroll
        for (int rs = 0; rs < 3; rs++) {
            int r = rg*3 + rs;
            if (r < 5) {
                #pragma unroll
                for (int c = 0; c < 9; c++)
                    s_u[lci*1440 + r*288 + c*32 + tx] = pf[rs*9+c];
            }
        }
        __syncthreads();
        if (cc < 15) load_cc(cc + 1);

        #pragma unroll
        for (int ci = 0; ci < 4; ci++) {
            const float* su  = s_u + ci*1440;
            const float* swc = s_w + (cc*4 + ci)*288 + (ty<<2);
            #pragma unroll
            for (int rr = 0; rr < 5; rr++) {
                unsigned long long vd[9];
                #pragma unroll
                for (int c = 0; c < 9; c++)
                    vd[c] = pk2(su[rr*288 + c*32 + tx]);
                #pragma unroll
                for (int kh = 0; kh < 3; kh++) {
                    int pr2 = rr - kh;
                    if (pr2 == 0 || pr2 == 2) {
                        int pr = pr2 >> 1;
                        #pragma unroll
                        for (int kw = 0; kw < 3; kw++) {
                            ulonglong2 wv = *(const ulonglong2*)(swc + (kh*3+kw)*32);
                            #pragma unroll
                            for (int pc = 0; pc < 4; pc++) {
                                int p = pr*4 + pc;
                                acc[0][p] = fma2(wv.x, vd[2*pc+kw], acc[0][p]);
                                acc[1][p] = fma2(wv.y, vd[2*pc+kw], acc[1][p]);
                            }
                        }
                    }
                }
            }
        }
        __syncthreads();
    }

    // ---- transpose (alias s_w) + scan B ----
    #pragma unroll
    for (int j = 0; j < 2; j++)
        #pragma unroll
        for (int p = 0; p < 8; p++) {
            float lo, hi;
            unpk2(acc[j][p], lo, hi);
            sm[((ty*4 + 2*j    )*8 + p)*33 + tx] = lo;
            sm[((ty*4 + 2*j + 1)*8 + p)*33 + tx] = hi;
        }
    __syncthreads();
    {
        int co_local = tid >> 3;
        int p = tid & 7;
        int h = h0 + (p >> 2);
        int w = w0 + (p & 3);
        int co = cg*32 + co_local;
        float v = 0.f, cnt = 0.f;
        #pragma unroll
        for (int t = 0; t < TT; t++) {
            v = 0.5f * v + sm[tid*33 + t];
            float sp = (v >= 1.0f) ? 1.0f : 0.0f;
            v -= sp;
            cnt += sp;
        }
        g_zb[((size_t)(b*CC + co)*HO + h)*WO + w] = cnt * (1.0f / 30.0f);
    }
}

// ============================================================
// u_bar: leaky temporal average
// ============================================================
__global__ __launch_bounds__(256) void ubar_k(const float* __restrict__ u)
{
    int pix = blockIdx.x * blockDim.x + threadIdx.x;
    if (pix >= BB*CC*HH*WW) return;
    const float* up = u + (size_t)pix * TT;
    float p = 1.0f;
    #pragma unroll
    for (int i = 0; i < 30; i++) p *= 0.9f;      // 0.9^30
    float p31 = p * 0.9f;
    float inv = 0.1f / (1.0f - p31);
    float acc = (1.0f + p) * up[29];
    float w = 0.9f;
    #pragma unroll
    for (int j = 28; j >= 0; j--) {
        acc += w * up[j];
        w *= 0.9f;
    }
    g_ubar[pix] = acc * inv;
}

// ============================================================
// final A: a = clip(conv(u_bar,W_in) + conv(z_a,W_aa), 0, 1)
// block: 8x8 px tile (grid.x 16) x ALL 64 co, b = grid.z
// thread: cq = tid&15 (co quad: pairs 2cq,2cq+1), pb = tid>>4 (2x2 px block)
// weights interleaved per pair: {w1lo,w1hi,w2lo,w2hi} -> 1 LDS.128 = 2 convs
// ============================================================
__global__ __launch_bounds__(256) void finalA_k(const float* __restrict__ Win,
                                                const float* __restrict__ Waa,
                                                float* __restrict__ outA)
{
    __shared__ float s_ubv[400];     // [4ci][10][10]
    __shared__ float s_zav[400];
    __shared__ float s_wv[4608];     // [4ci][9tap][32pair][4]

    int tid = threadIdx.x;
    int cq = tid & 15;
    int pb = tid >> 4;
    int pr0 = (pb >> 2) * 2;
    int pc0 = (pb & 3) * 2;
    int tile = blockIdx.x;           // 0..15
    int b    = blockIdx.z;
    int h0 = (tile >> 2) * 8, w0 = (tile & 3) * 8;

    unsigned long long accA[2][2], accB[2][2];
    #pragma unroll
    for (int i = 0; i < 2; i++)
        #pragma unroll
        for (int j = 0; j < 2; j++) { accA[i][j] = 0ull; accB[i][j] = 0ull; }

    for (int cc = 0; cc < 16; cc++) {
        int ci0 = cc * 4;
        // values
        for (int e = tid; e < 800; e += 256) {
            int a = (e >= 400);
            int i = e - a*400;
            int ci = i / 100; int rem = i % 100;
            int r = rem / 10, c = rem % 10;
            int gh = h0 - 1 + r, gw = w0 - 1 + c;
            bool ok = (gh >= 0) & (gh < HH) & (gw >= 0) & (gw < WW);
            float v = 0.f;
            if (ok) {
                size_t gi = ((size_t)(b*CC + ci0+ci)*HH + gh)*WW + gw;
                v = a ? g_za[gi] : g_ubar[gi];
            }
            (a ? s_zav : s_ubv)[i] = v;
        }
        // weights: linear STS, scattered LDG (L2-resident)
        for (int e = tid; e < 4608; e += 256) {
            int ci = e / 1152; int t1 = e % 1152;
            int tap = t1 / 128; int t2 = t1 % 128;
            int pair = t2 >> 2; int s = t2 & 3;
            int co = pair*2 + (s & 1);
            const float* W = (s < 2) ? Win : Waa;
            s_wv[e] = W[(size_t)co*576 + (ci0+ci)*9 + tap];
        }
        __syncthreads();

        #pragma unroll 2
        for (int ci = 0; ci < 4; ci++) {
            #pragma unroll
            for (int kh = 0; kh < 3; kh++) {
                ulonglong2 wa[3], wb[3];
                #pragma unroll
                for (int kw = 0; kw < 3; kw++) {
                    const float* wp = s_wv + ((ci*9 + kh*3+kw)*32 + 2*cq)*4;
                    wa[kw] = *(const ulonglong2*)wp;
                    wb[kw] = *(const ulonglong2*)(wp + 4);
                }
                #pragma unroll
                for (int pr = 0; pr < 2; pr++) {
                    int rr = pr0 + pr + kh;
                    unsigned long long vu[4], vz[4];
                    #pragma unroll
                    for (int c = 0; c < 4; c++) {
                        vu[c] = pk2(s_ubv[ci*100 + rr*10 + pc0 + c]);
                        vz[c] = pk2(s_zav[ci*100 + rr*10 + pc0 + c]);
                    }
                    #pragma unroll
                    for (int kw = 0; kw < 3; kw++)
                        #pragma unroll
                        for (int px = 0; px < 2; px++) {
                            accA[pr][px] = fma2(wa[kw].x, vu[px+kw], accA[pr][px]);
                            accA[pr][px] = fma2(wa[kw].y, vz[px+kw], accA[pr][px]);
                            accB[pr][px] = fma2(wb[kw].x, vu[px+kw], accB[pr][px]);
                            accB[pr][px] = fma2(wb[kw].y, vz[px+kw], accB[pr][px]);
                        }
                }
            }
        }
        __syncthreads();
    }

    int co0 = 4 * cq;
    #pragma unroll
    for (int pr = 0; pr < 2; pr++)
        #pragma unroll
        for (int px = 0; px < 2; px++) {
            int h = h0 + pr0 + pr;
            int w = w0 + pc0 + px;
            float lo, hi;
            unpk2(accA[pr][px], lo, hi);
            outA[((b*CC + co0    )*HH + h)*WW + w] = fminf(fmaxf(lo, 0.f), 1.f);
            outA[((b*CC + co0 + 1)*HH + h)*WW + w] = fminf(fmaxf(hi, 0.f), 1.f);
            unpk2(accB[pr][px], lo, hi);
            outA[((b*CC + co0 + 2)*HH + h)*WW + w] = fminf(fmaxf(lo, 0.f), 1.f);
            outA[((b*CC + co0 + 3)*HH + h)*WW + w] = fminf(fmaxf(hi, 0.f), 1.f);
        }
}

// ============================================================
// final B: b_out = clip(conv(a,W_down,s2) + conv(z_b,W_bb), 0, 1) on 16x16
// block: full 16x16 px x 16 co (grid: 4 cog, b); thread: cq=tid&3, pb=tid>>2 (2x2 px)
// ============================================================
__global__ __launch_bounds__(256) void finalB_k(const float* __restrict__ Wdn,
                                                const float* __restrict__ Wbb,
                                                const float* __restrict__ aIn,
                                                float* __restrict__ outB)
{
    __shared__ float s_av[4356];     // [4ci][33][33]  (stride-2 in-region, pad-hi)
    __shared__ float s_zv[1296];     // [4ci][18][18]  (halo 1)
    __shared__ float s_wv[1152];     // [4ci][9tap][8pair][4]

    int tid = threadIdx.x;
    int cq = tid & 3;
    int pb = tid >> 2;               // 0..63
    int pr0 = (pb >> 3) * 2;
    int pc0 = (pb & 7) * 2;
    int cog = blockIdx.x;            // 0..3
    int b   = blockIdx.z;

    unsigned long long accA[2][2], accB[2][2];
    #pragma unroll
    for (int i = 0; i < 2; i++)
        #pragma unroll
        for (int j = 0; j < 2; j++) { accA[i][j] = 0ull; accB[i][j] = 0ull; }

    for (int cc = 0; cc < 16; cc++) {
        int ci0 = cc * 4;
        // a tile: in coords 0..32, guard <32
        for (int e = tid; e < 4356; e += 256) {
            int ci = e / 1089; int i = e % 1089;
            int r = i / 33, c = i % 33;
            float v = 0.f;
            if (r < HH && c < WW)
                v = aIn[((size_t)(b*CC + ci0+ci)*HH + r)*WW + c];
            s_av[e] = v;
        }
        // z tile: halo 1
        for (int e = tid; e < 1296; e += 256) {
            int ci = e / 324; int i = e % 324;
            int r = i / 18, c = i % 18;
            int gh = r - 1, gw = c - 1;
            bool ok = (gh >= 0) & (gh < HO) & (gw >= 0) & (gw < WO);
            s_zv[e] = ok ? g_zb[((size_t)(b*CC + ci0+ci)*HO + gh)*WO + gw] : 0.f;
        }
        // weights
        for (int e = tid; e < 1152; e += 256) {
            int ci = e / 288; int t1 = e % 288;
            int tap = t1 / 32; int t2 = t1 % 32;
            int pair = t2 >> 2; int s = t2 & 3;
            int co = cog*16 + pair*2 + (s & 1);
            const float* W = (s < 2) ? Wdn : Wbb;
            s_wv[e] = W[(size_t)co*576 + (ci0+ci)*9 + tap];
        }
        __syncthreads();

        #pragma unroll 2
        for (int ci = 0; ci < 4; ci++) {
            #pragma unroll
            for (int kh = 0; kh < 3; kh++) {
                ulonglong2 wa[3], wb[3];
                #pragma unroll
                for (int kw = 0; kw < 3; kw++) {
                    const float* wp = s_wv + ((ci*9 + kh*3+kw)*8 + 2*cq)*4;
                    wa[kw] = *(const ulonglong2*)wp;
                    wb[kw] = *(const ulonglong2*)(wp + 4);
                }
                #pragma unroll
                for (int pr = 0; pr < 2; pr++) {
                    int ra = 2*(pr0 + pr) + kh;      // 0..32
                    int rz = pr0 + pr + kh;          // 0..17
                    unsigned long long va[5], vz[4];
                    #pragma unroll
                    for (int c = 0; c < 5; c++)
                        va[c] = pk2(s_av[ci*1089 + ra*33 + 2*pc0 + c]);
                    #pragma unroll
                    for (int c = 0; c < 4; c++)
                        vz[c] = pk2(s_zv[ci*324 + rz*18 + pc0 + c]);
                    #pragma unroll
                    for (int kw = 0; kw < 3; kw++)
                        #pragma unroll
                        for (int px = 0; px < 2; px++) {
                            accA[pr][px] = fma2(wa[kw].x, va[2*px+kw], accA[pr][px]);
                            accA[pr][px] = fma2(wa[kw].y, vz[px+kw],   accA[pr][px]);
                            accB[pr][px] = fma2(wb[kw].x, va[2*px+kw], accB[pr][px]);
                            accB[pr][px] = fma2(wb[kw].y, vz[px+kw],   accB[pr][px]);
                        }
                }
            }
        }
        __syncthreads();
    }

    int co0 = cog*16 + 4*cq;
    #pragma unroll
    for (int pr = 0; pr < 2; pr++)
        #pragma unroll
        for (int px = 0; px < 2; px++) {
            int h = pr0 + pr;
            int w = pc0 + px;
            float lo, hi;
            unpk2(accA[pr][px], lo, hi);
            outB[((b*CC + co0    )*HO + h)*WO + w] = fminf(fmaxf(lo, 0.f), 1.f);
            outB[((b*CC + co0 + 1)*HO + h)*WO + w] = fminf(fmaxf(hi, 0.f), 1.f);
            unpk2(accB[pr][px], lo, hi);
            outB[((b*CC + co0 + 2)*HO + h)*WO + w] = fminf(fmaxf(lo, 0.f), 1.f);
            outB[((b*CC + co0 + 3)*HO + h)*WO + w] = fminf(fmaxf(hi, 0.f), 1.f);
        }
}

// ============================================================
extern "C" void kernel_launch(void* const* d_in, const int* in_sizes, int n_in,
                              void* d_out, int out_size)
{
    (void)in_sizes; (void)n_in; (void)out_size;
    const float* u   = (const float*)d_in[0];
    const float* Win = (const float*)d_in[1];
    const float* Waa = (const float*)d_in[2];
    const float* Wdn = (const float*)d_in[3];
    const float* Wbb = (const float*)d_in[4];
    float* outA = (float*)d_out;                      // a: [16,64,32,32]
    float* outB = outA + BB*CC*HH*WW;                 // b: [16,64,16,16]

    cudaFuncSetAttribute(conv1_k, cudaFuncAttributeMaxDynamicSharedMemorySize, 98304);
    cudaFuncSetAttribute(conv2_k, cudaFuncAttributeMaxDynamicSharedMemorySize, 96768);

    ubar_k <<<(BB*CC*HH*WW + 255)/256, 256>>>(u);
    conv1_k<<<dim3(128, 2, BB), 256, 98304>>>(u, Win);
    conv2_k<<<dim3(32, 2, BB), 256, 96768>>>(Wdn);
    finalA_k<<<dim3(16, 1, BB), 256>>>(Win, Waa, outA);
    finalB_k<<<dim3(4, 1, BB), 256>>>(Wdn, Wbb, outA, outB);
}

// round 8
// speedup vs baseline: 1.7722x; 1.1796x over previous
#include <cuda_runtime.h>

#define BB 16
#define CC 64
#define HH 32
#define WW 32
#define TT 30
#define TP 32
#define HO 16
#define WO 16

// ---- scratch (static device memory; no allocations) ----
__device__ float g_sf[BB*CC*HH*WW*TP];   // spikes s_a as float (t padded to 32)
__device__ float g_za[BB*CC*HH*WW];
__device__ float g_zb[BB*CC*HO*WO];
__device__ float g_ubar[BB*CC*HH*WW];

// pre-interleaved weights
__device__ __align__(16) float g_wA [16*4608];   // finalA: [cc][ci4][tap9][pair32][4]
__device__ __align__(16) float g_wB [16*4608];   // finalB: same layout (Wdn/Wbb)
__device__ __align__(16) float g_wC1[2*18432];   // conv1:  [cg][(ci*9+tap)*32+co]
__device__ __align__(16) float g_wC2[2*18432];   // conv2:  same (Wdn)

// packed f32x2 helpers
static __device__ __forceinline__ unsigned long long pk2(float x) {
    unsigned long long r;
    asm("mov.b64 %0, {%1, %1};" : "=l"(r) : "f"(x));
    return r;
}
static __device__ __forceinline__ unsigned long long fma2(unsigned long long a,
                                                          unsigned long long b,
                                                          unsigned long long c) {
    unsigned long long d;
    asm("fma.rn.f32x2 %0, %1, %2, %3;" : "=l"(d) : "l"(a), "l"(b), "l"(c));
    return d;
}
static __device__ __forceinline__ void unpk2(unsigned long long v, float& lo, float& hi) {
    asm("mov.b64 {%0, %1}, %2;" : "=f"(lo), "=f"(hi) : "l"(v));
}

// ============================================================
// weight prep: scatter-read once, so every consumer does coalesced loads
// ============================================================
__global__ __launch_bounds__(256) void wprep_k(const float* __restrict__ Win,
                                               const float* __restrict__ Waa,
                                               const float* __restrict__ Wdn,
                                               const float* __restrict__ Wbb)
{
    int idx = blockIdx.x * 256 + threadIdx.x;
    if (idx < 147456) {                      // g_wA / g_wB (pair-interleaved)
        int half = idx / 73728;              // 0: A, 1: B
        int j = idx % 73728;
        int cc = j / 4608, e = j % 4608;
        int ci = e / 1152, t1 = e % 1152;
        int tap = t1 / 128, t2 = t1 % 128;
        int pair = t2 >> 2, s = t2 & 3;
        int co = pair*2 + (s & 1);
        const float* W;
        if (half == 0) W = (s < 2) ? Win : Waa;
        else           W = (s < 2) ? Wdn : Wbb;
        float v = W[(size_t)co*576 + (cc*4+ci)*9 + tap];
        if (half == 0) g_wA[j] = v; else g_wB[j] = v;
    } else if (idx < 221184) {               // g_wC1 / g_wC2 (conv layouts)
        int j = idx - 147456;
        int half = j / 36864;                // 0: conv1(Win), 1: conv2(Wdn)
        int k = j % 36864;
        int cg = k / 18432, r = k % 18432;
        int ci = r / 288, tap = (r % 288) / 32, co = r & 31;
        const float* W = half ? Wdn : Win;
        float v = W[(size_t)(cg*32+co)*576 + ci*9 + tap];
        if (half == 0) g_wC1[k] = v; else g_wC2[k] = v;
    }
}

// ============================================================
// conv1 + LIF scan A fused. Dynamic smem 98304 B:
//   s_w[64ci][9tap][32co] = 18432 floats (aliased by 256x33 transpose later)
//   s_u[8ci][4r][6c][32t] =  6144 floats
// ============================================================
__global__ __launch_bounds__(256) void conv1_k(const float* __restrict__ u)
{
    extern __shared__ float sm[];
    float* s_w = sm;             // 18432 floats
    float* s_u = sm + 18432;     // 6144 floats

    int tid = threadIdx.x;
    int tx = tid & 31;
    int ty = tid >> 5;
    int tile = blockIdx.x;            // 0..127
    int cg = blockIdx.y;              // 0..1
    int b  = blockIdx.z;              // 0..15
    int h0 = (tile >> 3) * 2;
    int w0 = (tile & 7) * 4;

    // ---- coalesced full weight preload ----
    {
        const float4* ws = (const float4*)(g_wC1 + (size_t)cg * 18432);
        float4* wd = (float4*)s_w;
        #pragma unroll
        for (int k = 0; k < 18; k++)
            wd[tid + k*256] = ws[tid + k*256];
    }

    unsigned long long acc[2][8];
    #pragma unroll
    for (int j = 0; j < 2; j++)
        #pragma unroll
        for (int p = 0; p < 8; p++) acc[j][p] = 0ull;

    const float* ubase = u + (size_t)(b*CC + ty) * HH*WW*TT;
    bool tok = (tx < TT);
    float pf[24];

    auto load_cc = [&](int cc) {
        const float* up = ubase + (size_t)cc * 8 * HH*WW*TT;
        #pragma unroll
        for (int r = 0; r < 4; r++) {
            int gh = h0 - 1 + r;
            bool hok = (gh >= 0) & (gh < HH);
            #pragma unroll
            for (int c = 0; c < 6; c++) {
                int gw = w0 - 1 + c;
                bool ok = tok & hok & (gw >= 0) & (gw < WW);
                pf[r*6+c] = ok ? up[((size_t)gh*WW + gw)*TT + tx] : 0.f;
            }
        }
    };

    load_cc(0);
    __syncthreads();      // weights visible

    for (int cc = 0; cc < 8; cc++) {
        #pragma unroll
        for (int r = 0; r < 4; r++)
            #pragma unroll
            for (int c = 0; c < 6; c++)
                s_u[ty*768 + r*192 + c*32 + tx] = pf[r*6+c];
        __syncthreads();
        if (cc < 7) load_cc(cc + 1);     // LDGs overlap compute

        #pragma unroll 4
        for (int ci = 0; ci < 8; ci++) {
            const float* su  = s_u + ci*768;
            const float* swc = s_w + (cc*8 + ci)*288 + (ty<<2);
            #pragma unroll
            for (int rr = 0; rr < 4; rr++) {
                unsigned long long vd[6];
                #pragma unroll
                for (int c = 0; c < 6; c++)
                    vd[c] = pk2(su[rr*192 + c*32 + tx]);
                #pragma unroll
                for (int kh = 0; kh < 3; kh++) {
                    int pr = rr - kh;
                    if (pr == 0 || pr == 1) {
                        #pragma unroll
                        for (int kw = 0; kw < 3; kw++) {
                            ulonglong2 wv = *(const ulonglong2*)(swc + (kh*3+kw)*32);
                            #pragma unroll
                            for (int pc = 0; pc < 4; pc++) {
                                int p = pr*4 + pc;
                                acc[0][p] = fma2(wv.x, vd[pc+kw], acc[0][p]);
                                acc[1][p] = fma2(wv.y, vd[pc+kw], acc[1][p]);
                            }
                        }
                    }
                }
            }
        }
        __syncthreads();
    }

    // ---- transpose into [copix][t] pitch 33 (aliases s_w region) ----
    #pragma unroll
    for (int j = 0; j < 2; j++)
        #pragma unroll
        for (int p = 0; p < 8; p++) {
            float lo, hi;
            unpk2(acc[j][p], lo, hi);
            sm[((ty*4 + 2*j    )*8 + p)*33 + tx] = lo;
            sm[((ty*4 + 2*j + 1)*8 + p)*33 + tx] = hi;
        }
    __syncthreads();

    {
        int co_local = tid >> 3;
        int p = tid & 7;
        int h = h0 + (p >> 2);
        int w = w0 + (p & 3);
        int co = cg*32 + co_local;
        size_t pixIdx = ((size_t)(b*CC + co)*HH + h)*WW + w;

        float out[32];
        float v = 0.f, cnt = 0.f;
        #pragma unroll
        for (int t = 0; t < TT; t++) {
            v = 0.5f * v + sm[tid*33 + t];
            float sp = (v >= 1.0f) ? 1.0f : 0.0f;
            v -= sp;
            cnt += sp;
            out[t] = sp;
        }
        out[30] = 0.f; out[31] = 0.f;
        float4* op = (float4*)&g_sf[pixIdx * TP];
        #pragma unroll
        for (int i = 0; i < 8; i++)
            op[i] = make_float4(out[4*i], out[4*i+1], out[4*i+2], out[4*i+3]);
        g_za[pixIdx] = cnt * (1.0f / 30.0f);
    }
}

// ============================================================
// conv2 (stride-2 SAME: in = 2*out + k) + LIF scan B fused.
// ============================================================
__global__ __launch_bounds__(256) void conv2_k()
{
    extern __shared__ float sm[];
    float* s_w = sm;
    float* s_u = sm + 18432;

    int tid = threadIdx.x;
    int tx = tid & 31;
    int ty = tid >> 5;
    int tile = blockIdx.x;            // 0..31
    int cg = blockIdx.y;
    int b  = blockIdx.z;
    int h0 = (tile >> 2) * 2;         // out coords
    int w0 = (tile & 3) * 4;

    // ---- coalesced full weight preload ----
    {
        const float4* ws = (const float4*)(g_wC2 + (size_t)cg * 18432);
        float4* wd = (float4*)s_w;
        #pragma unroll
        for (int k = 0; k < 18; k++)
            wd[tid + k*256] = ws[tid + k*256];
    }

    unsigned long long acc[2][8];
    #pragma unroll
    for (int j = 0; j < 2; j++)
        #pragma unroll
        for (int p = 0; p < 8; p++) acc[j][p] = 0ull;

    int lci = ty & 3;
    int rg  = ty >> 2;                // 0 -> rows 0..2, 1 -> rows 3..4
    const float* sfbase = g_sf + (size_t)(b*CC + lci) * HH*WW*TP;
    float pf[27];

    auto load_cc = [&](int cc) {
        const float* up = sfbase + (size_t)cc * 4 * HH*WW*TP;
        #pragma unroll
        for (int rs = 0; rs < 3; rs++) {
            int r = rg*3 + rs;
            if (r < 5) {
                int gh = 2*h0 + r;
                bool hok = (gh < HH);
                #pragma unroll
                for (int c = 0; c < 9; c++) {
                    int gw = 2*w0 + c;
                    bool ok = hok & (gw < WW);
                    pf[rs*9+c] = ok ? up[((size_t)gh*WW + gw)*TP + tx] : 0.f;
                }
            }
        }
    };

    load_cc(0);
    __syncthreads();

    for (int cc = 0; cc < 16; cc++) {
        #pragma unroll
        for (int rs = 0; rs < 3; rs++) {
            int r = rg*3 + rs;
            if (r < 5) {
                #pragma unroll
                for (int c = 0; c < 9; c++)
                    s_u[lci*1440 + r*288 + c*32 + tx] = pf[rs*9+c];
            }
        }
        __syncthreads();
        if (cc < 15) load_cc(cc + 1);

        #pragma unroll
        for (int ci = 0; ci < 4; ci++) {
            const float* su  = s_u + ci*1440;
            const float* swc = s_w + (cc*4 + ci)*288 + (ty<<2);
            #pragma unroll
            for (int rr = 0; rr < 5; rr++) {
                unsigned long long vd[9];
                #pragma unroll
                for (int c = 0; c < 9; c++)
                    vd[c] = pk2(su[rr*288 + c*32 + tx]);
                #pragma unroll
                for (int kh = 0; kh < 3; kh++) {
                    int pr2 = rr - kh;
                    if (pr2 == 0 || pr2 == 2) {
                        int pr = pr2 >> 1;
                        #pragma unroll
                        for (int kw = 0; kw < 3; kw++) {
                            ulonglong2 wv = *(const ulonglong2*)(swc + (kh*3+kw)*32);
                            #pragma unroll
                            for (int pc = 0; pc < 4; pc++) {
                                int p = pr*4 + pc;
                                acc[0][p] = fma2(wv.x, vd[2*pc+kw], acc[0][p]);
                                acc[1][p] = fma2(wv.y, vd[2*pc+kw], acc[1][p]);
                            }
                        }
                    }
                }
            }
        }
        __syncthreads();
    }

    // ---- transpose (alias s_w) + scan B ----
    #pragma unroll
    for (int j = 0; j < 2; j++)
        #pragma unroll
        for (int p = 0; p < 8; p++) {
            float lo, hi;
            unpk2(acc[j][p], lo, hi);
            sm[((ty*4 + 2*j    )*8 + p)*33 + tx] = lo;
            sm[((ty*4 + 2*j + 1)*8 + p)*33 + tx] = hi;
        }
    __syncthreads();
    {
        int co_local = tid >> 3;
        int p = tid & 7;
        int h = h0 + (p >> 2);
        int w = w0 + (p & 3);
        int co = cg*32 + co_local;
        float v = 0.f, cnt = 0.f;
        #pragma unroll
        for (int t = 0; t < TT; t++) {
            v = 0.5f * v + sm[tid*33 + t];
            float sp = (v >= 1.0f) ? 1.0f : 0.0f;
            v -= sp;
            cnt += sp;
        }
        g_zb[((size_t)(b*CC + co)*HO + h)*WO + w] = cnt * (1.0f / 30.0f);
    }
}

// ============================================================
// u_bar: leaky temporal average
// ============================================================
__global__ __launch_bounds__(256) void ubar_k(const float* __restrict__ u)
{
    int pix = blockIdx.x * blockDim.x + threadIdx.x;
    if (pix >= BB*CC*HH*WW) return;
    const float* up = u + (size_t)pix * TT;
    float p = 1.0f;
    #pragma unroll
    for (int i = 0; i < 30; i++) p *= 0.9f;      // 0.9^30
    float p31 = p * 0.9f;
    float inv = 0.1f / (1.0f - p31);
    float acc = (1.0f + p) * up[29];
    float w = 0.9f;
    #pragma unroll
    for (int j = 28; j >= 0; j--) {
        acc += w * up[j];
        w *= 0.9f;
    }
    g_ubar[pix] = acc * inv;
}

// ============================================================
// final A: a = clip(conv(u_bar,W_in) + conv(z_a,W_aa), 0, 1)
// block: 8x8 px tile x ALL 64 co. thread: cq=tid&15 (4 co), pb=tid>>4 (2x2 px)
// coalesced prepped weights + register prefetch of next chunk
// ============================================================
__global__ __launch_bounds__(256) void finalA_k(float* __restrict__ outA)
{
    __shared__ __align__(16) float s_ubv[400];     // [4ci][10][10]
    __shared__ __align__(16) float s_zav[400];
    __shared__ __align__(16) float s_wv[4608];     // [4ci][9tap][32pair][4]

    int tid = threadIdx.x;
    int cq = tid & 15;
    int pb = tid >> 4;
    int pr0 = (pb >> 2) * 2;
    int pc0 = (pb & 3) * 2;
    int tile = blockIdx.x;           // 0..15
    int b    = blockIdx.z;
    int h0 = (tile >> 2) * 8, w0 = (tile & 3) * 8;

    unsigned long long accA[2][2], accB[2][2];
    #pragma unroll
    for (int i = 0; i < 2; i++)
        #pragma unroll
        for (int j = 0; j < 2; j++) { accA[i][j] = 0ull; accB[i][j] = 0ull; }

    float2 pw[9];
    float  pv[4];

    auto ld_w = [&](int cc) {
        const float2* src = (const float2*)g_wA + (size_t)cc*2304 + tid;
        #pragma unroll
        for (int k = 0; k < 9; k++) pw[k] = src[k*256];
    };
    auto ld_v = [&](int cc) {
        #pragma unroll
        for (int k = 0; k < 4; k++) {
            int e = tid + k*256;
            float v = 0.f;
            if (e < 800) {
                int a = (e >= 400);
                int i = e - a*400;
                int ci = i / 100; int rem = i % 100;
                int r = rem / 10, c = rem % 10;
                int gh = h0 - 1 + r, gw = w0 - 1 + c;
                if (gh >= 0 && gh < HH && gw >= 0 && gw < WW) {
                    size_t gi = ((size_t)(b*CC + cc*4+ci)*HH + gh)*WW + gw;
                    v = a ? g_za[gi] : g_ubar[gi];
                }
            }
            pv[k] = v;
        }
    };

    ld_w(0); ld_v(0);

    for (int cc = 0; cc < 16; cc++) {
        {
            float2* wd = (float2*)s_wv + tid;
            #pragma unroll
            for (int k = 0; k < 9; k++) wd[k*256] = pw[k];
            #pragma unroll
            for (int k = 0; k < 4; k++) {
                int e = tid + k*256;
                if (e < 800) {
                    if (e >= 400) s_zav[e-400] = pv[k];
                    else          s_ubv[e]     = pv[k];
                }
            }
        }
        __syncthreads();
        if (cc < 15) { ld_w(cc+1); ld_v(cc+1); }

        #pragma unroll 2
        for (int ci = 0; ci < 4; ci++) {
            #pragma unroll
            for (int kh = 0; kh < 3; kh++) {
                ulonglong2 wa[3], wb[3];
                #pragma unroll
                for (int kw = 0; kw < 3; kw++) {
                    const float* wp = s_wv + ((ci*9 + kh*3+kw)*32 + 2*cq)*4;
                    wa[kw] = *(const ulonglong2*)wp;
                    wb[kw] = *(const ulonglong2*)(wp + 4);
                }
                #pragma unroll
                for (int pr = 0; pr < 2; pr++) {
                    int rr = pr0 + pr + kh;
                    unsigned long long vu[4], vz[4];
                    #pragma unroll
                    for (int c = 0; c < 4; c++) {
                        vu[c] = pk2(s_ubv[ci*100 + rr*10 + pc0 + c]);
                        vz[c] = pk2(s_zav[ci*100 + rr*10 + pc0 + c]);
                    }
                    #pragma unroll
                    for (int kw = 0; kw < 3; kw++)
                        #pragma unroll
                        for (int px = 0; px < 2; px++) {
                            accA[pr][px] = fma2(wa[kw].x, vu[px+kw], accA[pr][px]);
                            accA[pr][px] = fma2(wa[kw].y, vz[px+kw], accA[pr][px]);
                            accB[pr][px] = fma2(wb[kw].x, vu[px+kw], accB[pr][px]);
                            accB[pr][px] = fma2(wb[kw].y, vz[px+kw], accB[pr][px]);
                        }
                }
            }
        }
        __syncthreads();
    }

    int co0 = 4 * cq;
    #pragma unroll
    for (int pr = 0; pr < 2; pr++)
        #pragma unroll
        for (int px = 0; px < 2; px++) {
            int h = h0 + pr0 + pr;
            int w = w0 + pc0 + px;
            float lo, hi;
            unpk2(accA[pr][px], lo, hi);
            outA[((b*CC + co0    )*HH + h)*WW + w] = fminf(fmaxf(lo, 0.f), 1.f);
            outA[((b*CC + co0 + 1)*HH + h)*WW + w] = fminf(fmaxf(hi, 0.f), 1.f);
            unpk2(accB[pr][px], lo, hi);
            outA[((b*CC + co0 + 2)*HH + h)*WW + w] = fminf(fmaxf(lo, 0.f), 1.f);
            outA[((b*CC + co0 + 3)*HH + h)*WW + w] = fminf(fmaxf(hi, 0.f), 1.f);
        }
}

// ============================================================
// final B: b_out = clip(conv(a,W_down,s2) + conv(z_b,W_bb), 0, 1) on 16x16
// block: 8x8 out-px tile x ALL 64 co (grid: 4 tiles, b)
// thread: cq=tid&15 (4 co), pb=tid>>4 (2x2 px). prefetched chunks.
// ============================================================
__global__ __launch_bounds__(256) void finalB_k(const float* __restrict__ aIn,
                                                float* __restrict__ outB)
{
    __shared__ __align__(16) float s_av[1156];     // [4ci][17][17] (in-region, pad-hi)
    __shared__ __align__(16) float s_zv[400];      // [4ci][10][10] (halo 1)
    __shared__ __align__(16) float s_wv[4608];     // [4ci][9tap][32pair][4]

    int tid = threadIdx.x;
    int cq = tid & 15;
    int pb = tid >> 4;
    int pr0 = (pb >> 2) * 2;
    int pc0 = (pb & 3) * 2;
    int tile = blockIdx.x;           // 0..3
    int b    = blockIdx.z;
    int h0 = (tile >> 1) * 8, w0 = (tile & 1) * 8;   // out coords

    unsigned long long accA[2][2], accB[2][2];
    #pragma unroll
    for (int i = 0; i < 2; i++)
        #pragma unroll
        for (int j = 0; j < 2; j++) { accA[i][j] = 0ull; accB[i][j] = 0ull; }

    float2 pw[9];
    float  pa[5];
    float  pz[2];

    auto ld_w = [&](int cc) {
        const float2* src = (const float2*)g_wB + (size_t)cc*2304 + tid;
        #pragma unroll
        for (int k = 0; k < 9; k++) pw[k] = src[k*256];
    };
    auto ld_a = [&](int cc) {
        #pragma unroll
        for (int k = 0; k < 5; k++) {
            int e = tid + k*256;
            float v = 0.f;
            if (e < 1156) {
                int ci = e / 289; int i = e % 289;
                int r = i / 17, c = i % 17;
                int gh = 2*h0 + r, gw = 2*w0 + c;
                if (gh < HH && gw < WW)
                    v = aIn[((size_t)(b*CC + cc*4+ci)*HH + gh)*WW + gw];
            }
            pa[k] = v;
        }
    };
    auto ld_z = [&](int cc) {
        #pragma unroll
        for (int k = 0; k < 2; k++) {
            int e = tid + k*256;
            float v = 0.f;
            if (e < 400) {
                int ci = e / 100; int i = e % 100;
                int r = i / 10, c = i % 10;
                int gh = h0 - 1 + r, gw = w0 - 1 + c;
                if (gh >= 0 && gh < HO && gw >= 0 && gw < WO)
                    v = g_zb[((size_t)(b*CC + cc*4+ci)*HO + gh)*WO + gw];
            }
            pz[k] = v;
        }
    };

    ld_w(0); ld_a(0); ld_z(0);

    for (int cc = 0; cc < 16; cc++) {
        {
            float2* wd = (float2*)s_wv + tid;
            #pragma unroll
            for (int k = 0; k < 9; k++) wd[k*256] = pw[k];
            #pragma unroll
            for (int k = 0; k < 5; k++) {
                int e = tid + k*256;
                if (e < 1156) s_av[e] = pa[k];
            }
            #pragma unroll
            for (int k = 0; k < 2; k++) {
                int e = tid + k*256;
                if (e < 400) s_zv[e] = pz[k];
            }
        }
        __syncthreads();
        if (cc < 15) { ld_w(cc+1); ld_a(cc+1); ld_z(cc+1); }

        #pragma unroll 2
        for (int ci = 0; ci < 4; ci++) {
            #pragma unroll
            for (int kh = 0; kh < 3; kh++) {
                ulonglong2 wa[3], wb[3];
                #pragma unroll
                for (int kw = 0; kw < 3; kw++) {
                    const float* wp = s_wv + ((ci*9 + kh*3+kw)*32 + 2*cq)*4;
                    wa[kw] = *(const ulonglong2*)wp;
                    wb[kw] = *(const ulonglong2*)(wp + 4);
                }
                #pragma unroll
                for (int pr = 0; pr < 2; pr++) {
                    int ra = 2*(pr0 + pr) + kh;      // 0..16
                    int rz = pr0 + pr + kh;          // 0..9
                    unsigned long long va[5], vz[4];
                    #pragma unroll
                    for (int c = 0; c < 5; c++)
                        va[c] = pk2(s_av[ci*289 + ra*17 + 2*pc0 + c]);
                    #pragma unroll
                    for (int c = 0; c < 4; c++)
                        vz[c] = pk2(s_zv[ci*100 + rz*10 + pc0 + c]);
                    #pragma unroll
                    for (int kw = 0; kw < 3; kw++)
                        #pragma unroll
                        for (int px = 0; px < 2; px++) {
                            accA[pr][px] = fma2(wa[kw].x, va[2*px+kw], accA[pr][px]);
                            accA[pr][px] = fma2(wa[kw].y, vz[px+kw],   accA[pr][px]);
                            accB[pr][px] = fma2(wb[kw].x, va[2*px+kw], accB[pr][px]);
                            accB[pr][px] = fma2(wb[kw].y, vz[px+kw],   accB[pr][px]);
                        }
                }
            }
        }
        __syncthreads();
    }

    int co0 = 4 * cq;
    #pragma unroll
    for (int pr = 0; pr < 2; pr++)
        #pragma unroll
        for (int px = 0; px < 2; px++) {
            int h = h0 + pr0 + pr;
            int w = w0 + pc0 + px;
            float lo, hi;
            unpk2(accA[pr][px], lo, hi);
            outB[((b*CC + co0    )*HO + h)*WO + w] = fminf(fmaxf(lo, 0.f), 1.f);
            outB[((b*CC + co0 + 1)*HO + h)*WO + w] = fminf(fmaxf(hi, 0.f), 1.f);
            unpk2(accB[pr][px], lo, hi);
            outB[((b*CC + co0 + 2)*HO + h)*WO + w] = fminf(fmaxf(lo, 0.f), 1.f);
            outB[((b*CC + co0 + 3)*HO + h)*WO + w] = fminf(fmaxf(hi, 0.f), 1.f);
        }
}

// ============================================================
extern "C" void kernel_launch(void* const* d_in, const int* in_sizes, int n_in,
                              void* d_out, int out_size)
{
    (void)in_sizes; (void)n_in; (void)out_size;
    const float* u   = (const float*)d_in[0];
    const float* Win = (const float*)d_in[1];
    const float* Waa = (const float*)d_in[2];
    const float* Wdn = (const float*)d_in[3];
    const float* Wbb = (const float*)d_in[4];
    float* outA = (float*)d_out;                      // a: [16,64,32,32]
    float* outB = outA + BB*CC*HH*WW;                 // b: [16,64,16,16]

    cudaFuncSetAttribute(conv1_k, cudaFuncAttributeMaxDynamicSharedMemorySize, 98304);
    cudaFuncSetAttribute(conv2_k, cudaFuncAttributeMaxDynamicSharedMemorySize, 96768);

    wprep_k<<<864, 256>>>(Win, Waa, Wdn, Wbb);
    ubar_k <<<(BB*CC*HH*WW + 255)/256, 256>>>(u);
    conv1_k<<<dim3(128, 2, BB), 256, 98304>>>(u);
    conv2_k<<<dim3(32, 2, BB), 256, 96768>>>();
    finalA_k<<<dim3(16, 1, BB), 256>>>(outA);
    finalB_k<<<dim3(4, 1, BB), 256>>>(outA, outB);
}

// round 9
// speedup vs baseline: 1.7786x; 1.0036x over previous
#include <cuda_runtime.h>

#define BB 16
#define CC 64
#define HH 32
#define WW 32
#define TT 30
#define TP 32
#define HO 16
#define WO 16

// ---- scratch (static device memory; no allocations) ----
__device__ float g_sf[BB*CC*HH*WW*TP];   // spikes s_a as float (t padded to 32)
__device__ float g_za[BB*CC*HH*WW];
__device__ float g_zb[BB*CC*HO*WO];
__device__ float g_ubar[BB*CC*HH*WW];

// pre-interleaved weights
__device__ __align__(16) float g_wA [16*4608];   // finalA: [cc][ci4][tap9][pair32][4]
__device__ __align__(16) float g_wB [16*4608];   // finalB: same layout (Wdn/Wbb)
__device__ __align__(16) float g_wC1[2*18432];   // conv1:  [cg][(ci*9+tap)*32+co]
__device__ __align__(16) float g_wC2[2*18432];   // conv2:  same (Wdn)

// packed f32x2 helpers
static __device__ __forceinline__ unsigned long long pk2(float x) {
    unsigned long long r;
    asm("mov.b64 %0, {%1, %1};" : "=l"(r) : "f"(x));
    return r;
}
static __device__ __forceinline__ unsigned long long fma2(unsigned long long a,
                                                          unsigned long long b,
                                                          unsigned long long c) {
    unsigned long long d;
    asm("fma.rn.f32x2 %0, %1, %2, %3;" : "=l"(d) : "l"(a), "l"(b), "l"(c));
    return d;
}
static __device__ __forceinline__ void unpk2(unsigned long long v, float& lo, float& hi) {
    asm("mov.b64 {%0, %1}, %2;" : "=f"(lo), "=f"(hi) : "l"(v));
}

// ============================================================
// weight prep: scatter-read once, so every consumer does coalesced loads
// ============================================================
__global__ __launch_bounds__(256) void wprep_k(const float* __restrict__ Win,
                                               const float* __restrict__ Waa,
                                               const float* __restrict__ Wdn,
                                               const float* __restrict__ Wbb)
{
    int idx = blockIdx.x * 256 + threadIdx.x;
    if (idx < 147456) {                      // g_wA / g_wB (pair-interleaved)
        int half = idx / 73728;              // 0: A, 1: B
        int j = idx % 73728;
        int cc = j / 4608, e = j % 4608;
        int ci = e / 1152, t1 = e % 1152;
        int tap = t1 / 128, t2 = t1 % 128;
        int pair = t2 >> 2, s = t2 & 3;
        int co = pair*2 + (s & 1);
        const float* W;
        if (half == 0) W = (s < 2) ? Win : Waa;
        else           W = (s < 2) ? Wdn : Wbb;
        float v = W[(size_t)co*576 + (cc*4+ci)*9 + tap];
        if (half == 0) g_wA[j] = v; else g_wB[j] = v;
    } else if (idx < 221184) {               // g_wC1 / g_wC2 (conv layouts)
        int j = idx - 147456;
        int half = j / 36864;                // 0: conv1(Win), 1: conv2(Wdn)
        int k = j % 36864;
        int cg = k / 18432, r = k % 18432;
        int ci = r / 288, tap = (r % 288) / 32, co = r & 31;
        const float* W = half ? Wdn : Win;
        float v = W[(size_t)(cg*32+co)*576 + ci*9 + tap];
        if (half == 0) g_wC1[k] = v; else g_wC2[k] = v;
    }
}

// ============================================================
// conv1 + LIF scan A fused.
// block tile: 2x4 out px, 32 co (cg half), 32 t lanes. Per thread: 2x2 px, 8 co.
// ty = {pg(1b): col-half, cog(2b): co-octet}. Sliding 2-row register cache.
// smem: s_w 18432 floats (all weights for this cg) | s_u[8ci][4r][6c][32t]
// ============================================================
__global__ __launch_bounds__(256) void conv1_k(const float* __restrict__ u)
{
    extern __shared__ float sm[];
    float* s_w = sm;             // 18432 floats
    float* s_u = sm + 18432;     // 6144 floats

    int tid = threadIdx.x;
    int tx = tid & 31;
    int ty = tid >> 5;
    int pg  = ty >> 2;           // 0..1 : pixel column half
    int cog = ty & 3;            // 0..3 : co octet
    int tile = blockIdx.x;       // 0..127
    int cg = blockIdx.y;         // 0..1
    int b  = blockIdx.z;         // 0..15
    int h0 = (tile >> 3) * 2;
    int w0 = (tile & 7) * 4;

    // ---- coalesced full weight preload ----
    {
        const float4* ws = (const float4*)(g_wC1 + (size_t)cg * 18432);
        float4* wd = (float4*)s_w;
        #pragma unroll
        for (int k = 0; k < 18; k++)
            wd[tid + k*256] = ws[tid + k*256];
    }

    // acc[pr][pcl][k]: px=(pr, pg*2+pcl), co pair = cog*8 + 2k,2k+1
    unsigned long long acc[2][2][4];
    #pragma unroll
    for (int i = 0; i < 2; i++)
        #pragma unroll
        for (int j = 0; j < 2; j++)
            #pragma unroll
            for (int k = 0; k < 4; k++) acc[i][j][k] = 0ull;

    const float* ubase = u + (size_t)(b*CC + ty) * HH*WW*TT;   // staging: ty = ci
    bool tok = (tx < TT);
    float pf[24];

    auto load_cc = [&](int cc) {
        const float* up = ubase + (size_t)cc * 8 * HH*WW*TT;
        #pragma unroll
        for (int r = 0; r < 4; r++) {
            int gh = h0 - 1 + r;
            bool hok = (gh >= 0) & (gh < HH);
            #pragma unroll
            for (int c = 0; c < 6; c++) {
                int gw = w0 - 1 + c;
                bool ok = tok & hok & (gw >= 0) & (gw < WW);
                pf[r*6+c] = ok ? up[((size_t)gh*WW + gw)*TT + tx] : 0.f;
            }
        }
    };

    load_cc(0);
    __syncthreads();      // weights visible

    for (int cc = 0; cc < 8; cc++) {
        #pragma unroll
        for (int r = 0; r < 4; r++)
            #pragma unroll
            for (int c = 0; c < 6; c++)
                s_u[ty*768 + r*192 + c*32 + tx] = pf[r*6+c];
        __syncthreads();
        if (cc < 7) load_cc(cc + 1);     // LDGs overlap compute

        #pragma unroll 2
        for (int ci = 0; ci < 8; ci++) {
            const float* su  = s_u + ci*768 + (pg*2)*32 + tx;   // col c -> +c*32, row r -> +r*192
            const float* swc = s_w + (cc*8 + ci)*288 + cog*8;

            unsigned long long ra[4], rb[4];
            #pragma unroll
            for (int c = 0; c < 4; c++) ra[c] = pk2(su[0*192 + c*32]);
            #pragma unroll
            for (int c = 0; c < 4; c++) rb[c] = pk2(su[1*192 + c*32]);

            #pragma unroll
            for (int kh = 0; kh < 3; kh++) {
                ulonglong2 wv0[3], wv1[3];
                #pragma unroll
                for (int kw = 0; kw < 3; kw++) {
                    const float* wp = swc + (kh*3+kw)*32;
                    wv0[kw] = *(const ulonglong2*)wp;
                    wv1[kw] = *(const ulonglong2*)(wp + 4);
                }
                #pragma unroll
                for (int kw = 0; kw < 3; kw++)
                    #pragma unroll
                    for (int pcl = 0; pcl < 2; pcl++) {
                        unsigned long long va = ra[pcl+kw];
                        unsigned long long vb = rb[pcl+kw];
                        acc[0][pcl][0] = fma2(wv0[kw].x, va, acc[0][pcl][0]);
                        acc[0][pcl][1] = fma2(wv0[kw].y, va, acc[0][pcl][1]);
                        acc[0][pcl][2] = fma2(wv1[kw].x, va, acc[0][pcl][2]);
                        acc[0][pcl][3] = fma2(wv1[kw].y, va, acc[0][pcl][3]);
                        acc[1][pcl][0] = fma2(wv0[kw].x, vb, acc[1][pcl][0]);
                        acc[1][pcl][1] = fma2(wv0[kw].y, vb, acc[1][pcl][1]);
                        acc[1][pcl][2] = fma2(wv1[kw].x, vb, acc[1][pcl][2]);
                        acc[1][pcl][3] = fma2(wv1[kw].y, vb, acc[1][pcl][3]);
                    }
                if (kh < 2) {
                    #pragma unroll
                    for (int c = 0; c < 4; c++) {
                        ra[c] = rb[c];
                        rb[c] = pk2(su[(kh+2)*192 + c*32]);
                    }
                }
            }
        }
        __syncthreads();
    }

    // ---- transpose into [copix][t] pitch 33 (aliases s_w region) ----
    #pragma unroll
    for (int pr = 0; pr < 2; pr++)
        #pragma unroll
        for (int pcl = 0; pcl < 2; pcl++)
            #pragma unroll
            for (int k = 0; k < 4; k++) {
                float lo, hi;
                unpk2(acc[pr][pcl][k], lo, hi);
                int px = pr*4 + pg*2 + pcl;
                sm[((cog*8 + 2*k    )*8 + px)*33 + tx] = lo;
                sm[((cog*8 + 2*k + 1)*8 + px)*33 + tx] = hi;
            }
    __syncthreads();

    {
        int co_local = tid >> 3;
        int p = tid & 7;
        int h = h0 + (p >> 2);
        int w = w0 + (p & 3);
        int co = cg*32 + co_local;
        size_t pixIdx = ((size_t)(b*CC + co)*HH + h)*WW + w;

        float out[32];
        float v = 0.f, cnt = 0.f;
        #pragma unroll
        for (int t = 0; t < TT; t++) {
            v = 0.5f * v + sm[tid*33 + t];
            float sp = (v >= 1.0f) ? 1.0f : 0.0f;
            v -= sp;
            cnt += sp;
            out[t] = sp;
        }
        out[30] = 0.f; out[31] = 0.f;
        float4* op = (float4*)&g_sf[pixIdx * TP];
        #pragma unroll
        for (int i = 0; i < 8; i++)
            op[i] = make_float4(out[4*i], out[4*i+1], out[4*i+2], out[4*i+3]);
        g_za[pixIdx] = cnt * (1.0f / 30.0f);
    }
}

// ============================================================
// conv2 (stride-2 SAME: in = 2*out + k) + LIF scan B fused.
// Per thread: 2x2 out px, 8 co. ty = {pg, cog}.
// ============================================================
__global__ __launch_bounds__(256) void conv2_k()
{
    extern __shared__ float sm[];
    float* s_w = sm;
    float* s_u = sm + 18432;

    int tid = threadIdx.x;
    int tx = tid & 31;
    int ty = tid >> 5;
    int pg  = ty >> 2;
    int cog = ty & 3;
    int tile = blockIdx.x;            // 0..31
    int cg = blockIdx.y;
    int b  = blockIdx.z;
    int h0 = (tile >> 2) * 2;         // out coords
    int w0 = (tile & 3) * 4;

    // ---- coalesced full weight preload ----
    {
        const float4* ws = (const float4*)(g_wC2 + (size_t)cg * 18432);
        float4* wd = (float4*)s_w;
        #pragma unroll
        for (int k = 0; k < 18; k++)
            wd[tid + k*256] = ws[tid + k*256];
    }

    unsigned long long acc[2][2][4];
    #pragma unroll
    for (int i = 0; i < 2; i++)
        #pragma unroll
        for (int j = 0; j < 2; j++)
            #pragma unroll
            for (int k = 0; k < 4; k++) acc[i][j][k] = 0ull;

    int lci = ty & 3;
    int rg  = ty >> 2;                // 0 -> rows 0..2, 1 -> rows 3..4
    const float* sfbase = g_sf + (size_t)(b*CC + lci) * HH*WW*TP;
    float pf[27];

    auto load_cc = [&](int cc) {
        const float* up = sfbase + (size_t)cc * 4 * HH*WW*TP;
        #pragma unroll
        for (int rs = 0; rs < 3; rs++) {
            int r = rg*3 + rs;
            if (r < 5) {
                int gh = 2*h0 + r;
                bool hok = (gh < HH);
                #pragma unroll
                for (int c = 0; c < 9; c++) {
                    int gw = 2*w0 + c;
                    bool ok = hok & (gw < WW);
                    pf[rs*9+c] = ok ? up[((size_t)gh*WW + gw)*TP + tx] : 0.f;
                }
            }
        }
    };

    load_cc(0);
    __syncthreads();

    for (int cc = 0; cc < 16; cc++) {
        #pragma unroll
        for (int rs = 0; rs < 3; rs++) {
            int r = rg*3 + rs;
            if (r < 5) {
                #pragma unroll
                for (int c = 0; c < 9; c++)
                    s_u[lci*1440 + r*288 + c*32 + tx] = pf[rs*9+c];
            }
        }
        __syncthreads();
        if (cc < 15) load_cc(cc + 1);

        #pragma unroll 2
        for (int ci = 0; ci < 4; ci++) {
            const float* su  = s_u + ci*1440 + (pg*4)*32 + tx;   // col c -> +c*32
            const float* swc = s_w + (cc*4 + ci)*288 + cog*8;

            #pragma unroll
            for (int kh = 0; kh < 3; kh++) {
                ulonglong2 wv0[3], wv1[3];
                #pragma unroll
                for (int kw = 0; kw < 3; kw++) {
                    const float* wp = swc + (kh*3+kw)*32;
                    wv0[kw] = *(const ulonglong2*)wp;
                    wv1[kw] = *(const ulonglong2*)(wp + 4);
                }
                #pragma unroll
                for (int pr = 0; pr < 2; pr++) {
                    int r = 2*pr + kh;
                    unsigned long long vd[5];
                    #pragma unroll
                    for (int c = 0; c < 5; c++)
                        vd[c] = pk2(su[r*288 + c*32]);
                    #pragma unroll
                    for (int kw = 0; kw < 3; kw++)
                        #pragma unroll
                        for (int pcl = 0; pcl < 2; pcl++) {
                            unsigned long long v = vd[2*pcl + kw];
                            acc[pr][pcl][0] = fma2(wv0[kw].x, v, acc[pr][pcl][0]);
                            acc[pr][pcl][1] = fma2(wv0[kw].y, v, acc[pr][pcl][1]);
                            acc[pr][pcl][2] = fma2(wv1[kw].x, v, acc[pr][pcl][2]);
                            acc[pr][pcl][3] = fma2(wv1[kw].y, v, acc[pr][pcl][3]);
                        }
                }
            }
        }
        __syncthreads();
    }

    // ---- transpose (alias s_w) + scan B ----
    #pragma unroll
    for (int pr = 0; pr < 2; pr++)
        #pragma unroll
        for (int pcl = 0; pcl < 2; pcl++)
            #pragma unroll
            for (int k = 0; k < 4; k++) {
                float lo, hi;
                unpk2(acc[pr][pcl][k], lo, hi);
                int px = pr*4 + pg*2 + pcl;
                sm[((cog*8 + 2*k    )*8 + px)*33 + tx] = lo;
                sm[((cog*8 + 2*k + 1)*8 + px)*33 + tx] = hi;
            }
    __syncthreads();
    {
        int co_local = tid >> 3;
        int p = tid & 7;
        int h = h0 + (p >> 2);
        int w = w0 + (p & 3);
        int co = cg*32 + co_local;
        float v = 0.f, cnt = 0.f;
        #pragma unroll
        for (int t = 0; t < TT; t++) {
            v = 0.5f * v + sm[tid*33 + t];
            float sp = (v >= 1.0f) ? 1.0f : 0.0f;
            v -= sp;
            cnt += sp;
        }
        g_zb[((size_t)(b*CC + co)*HO + h)*WO + w] = cnt * (1.0f / 30.0f);
    }
}

// ============================================================
// u_bar: leaky temporal average (float2 loads halve L1 wavefronts)
// ============================================================
__global__ __launch_bounds__(256) void ubar_k(const float* __restrict__ u)
{
    int pix = blockIdx.x * blockDim.x + threadIdx.x;
    if (pix >= BB*CC*HH*WW) return;
    const float2* up2 = (const float2*)(u + (size_t)pix * TT);
    float uu[30];
    #pragma unroll
    for (int i = 0; i < 15; i++) {
        float2 v = up2[i];
        uu[2*i] = v.x; uu[2*i+1] = v.y;
    }
    float p = 1.0f;
    #pragma unroll
    for (int i = 0; i < 30; i++) p *= 0.9f;      // 0.9^30
    float p31 = p * 0.9f;
    float inv = 0.1f / (1.0f - p31);
    float acc = (1.0f + p) * uu[29];
    float w = 0.9f;
    #pragma unroll
    for (int j = 28; j >= 0; j--) {
        acc += w * uu[j];
        w *= 0.9f;
    }
    g_ubar[pix] = acc * inv;
}

// ============================================================
// final A: a = clip(conv(u_bar,W_in) + conv(z_a,W_aa), 0, 1)
// block: 8x8 px tile x ALL 64 co. thread: cq=tid&15 (4 co), pb=tid>>4 (2x2 px)
// sliding 2-row cache for vu/vz across kh
// ============================================================
__global__ __launch_bounds__(256) void finalA_k(float* __restrict__ outA)
{
    __shared__ __align__(16) float s_ubv[400];     // [4ci][10][10]
    __shared__ __align__(16) float s_zav[400];
    __shared__ __align__(16) float s_wv[4608];     // [4ci][9tap][32pair][4]

    int tid = threadIdx.x;
    int cq = tid & 15;
    int pb = tid >> 4;
    int pr0 = (pb >> 2) * 2;
    int pc0 = (pb & 3) * 2;
    int tile = blockIdx.x;           // 0..15
    int b    = blockIdx.z;
    int h0 = (tile >> 2) * 8, w0 = (tile & 3) * 8;

    unsigned long long accA[2][2], accB[2][2];
    #pragma unroll
    for (int i = 0; i < 2; i++)
        #pragma unroll
        for (int j = 0; j < 2; j++) { accA[i][j] = 0ull; accB[i][j] = 0ull; }

    float2 pw[9];
    float  pv[4];

    auto ld_w = [&](int cc) {
        const float2* src = (const float2*)g_wA + (size_t)cc*2304 + tid;
        #pragma unroll
        for (int k = 0; k < 9; k++) pw[k] = src[k*256];
    };
    auto ld_v = [&](int cc) {
        #pragma unroll
        for (int k = 0; k < 4; k++) {
            int e = tid + k*256;
            float v = 0.f;
            if (e < 800) {
                int a = (e >= 400);
                int i = e - a*400;
                int ci = i / 100; int rem = i % 100;
                int r = rem / 10, c = rem % 10;
                int gh = h0 - 1 + r, gw = w0 - 1 + c;
                if (gh >= 0 && gh < HH && gw >= 0 && gw < WW) {
                    size_t gi = ((size_t)(b*CC + cc*4+ci)*HH + gh)*WW + gw;
                    v = a ? g_za[gi] : g_ubar[gi];
                }
            }
            pv[k] = v;
        }
    };

    ld_w(0); ld_v(0);

    for (int cc = 0; cc < 16; cc++) {
        {
            float2* wd = (float2*)s_wv + tid;
            #pragma unroll
            for (int k = 0; k < 9; k++) wd[k*256] = pw[k];
            #pragma unroll
            for (int k = 0; k < 4; k++) {
                int e = tid + k*256;
                if (e < 800) {
                    if (e >= 400) s_zav[e-400] = pv[k];
                    else          s_ubv[e]     = pv[k];
                }
            }
        }
        __syncthreads();
        if (cc < 15) { ld_w(cc+1); ld_v(cc+1); }

        #pragma unroll 2
        for (int ci = 0; ci < 4; ci++) {
            // sliding cache: rows pr0+kh, pr0+kh+1
            unsigned long long ua[4], ub[4], za[4], zb[4];
            #pragma unroll
            for (int c = 0; c < 4; c++) {
                ua[c] = pk2(s_ubv[ci*100 + (pr0  )*10 + pc0 + c]);
                za[c] = pk2(s_zav[ci*100 + (pr0  )*10 + pc0 + c]);
                ub[c] = pk2(s_ubv[ci*100 + (pr0+1)*10 + pc0 + c]);
                zb[c] = pk2(s_zav[ci*100 + (pr0+1)*10 + pc0 + c]);
            }
            #pragma unroll
            for (int kh = 0; kh < 3; kh++) {
                ulonglong2 wa[3], wb[3];
                #pragma unroll
                for (int kw = 0; kw < 3; kw++) {
                    const float* wp = s_wv + ((ci*9 + kh*3+kw)*32 + 2*cq)*4;
                    wa[kw] = *(const ulonglong2*)wp;
                    wb[kw] = *(const ulonglong2*)(wp + 4);
                }
                #pragma unroll
                for (int kw = 0; kw < 3; kw++)
                    #pragma unroll
                    for (int px = 0; px < 2; px++) {
                        accA[0][px] = fma2(wa[kw].x, ua[px+kw], accA[0][px]);
                        accA[0][px] = fma2(wa[kw].y, za[px+kw], accA[0][px]);
                        accB[0][px] = fma2(wb[kw].x, ua[px+kw], accB[0][px]);
                        accB[0][px] = fma2(wb[kw].y, za[px+kw], accB[0][px]);
                        accA[1][px] = fma2(wa[kw].x, ub[px+kw], accA[1][px]);
                        accA[1][px] = fma2(wa[kw].y, zb[px+kw], accA[1][px]);
                        accB[1][px] = fma2(wb[kw].x, ub[px+kw], accB[1][px]);
                        accB[1][px] = fma2(wb[kw].y, zb[px+kw], accB[1][px]);
                    }
                if (kh < 2) {
                    #pragma unroll
                    for (int c = 0; c < 4; c++) {
                        ua[c] = ub[c]; za[c] = zb[c];
                        ub[c] = pk2(s_ubv[ci*100 + (pr0+kh+2)*10 + pc0 + c]);
                        zb[c] = pk2(s_zav[ci*100 + (pr0+kh+2)*10 + pc0 + c]);
                    }
                }
            }
        }
        __syncthreads();
    }

    int co0 = 4 * cq;
    #pragma unroll
    for (int pr = 0; pr < 2; pr++)
        #pragma unroll
        for (int px = 0; px < 2; px++) {
            int h = h0 + pr0 + pr;
            int w = w0 + pc0 + px;
            float lo, hi;
            unpk2(accA[pr][px], lo, hi);
            outA[((b*CC + co0    )*HH + h)*WW + w] = fminf(fmaxf(lo, 0.f), 1.f);
            outA[((b*CC + co0 + 1)*HH + h)*WW + w] = fminf(fmaxf(hi, 0.f), 1.f);
            unpk2(accB[pr][px], lo, hi);
            outA[((b*CC + co0 + 2)*HH + h)*WW + w] = fminf(fmaxf(lo, 0.f), 1.f);
            outA[((b*CC + co0 + 3)*HH + h)*WW + w] = fminf(fmaxf(hi, 0.f), 1.f);
        }
}

// ============================================================
// final B: b_out = clip(conv(a,W_down,s2) + conv(z_b,W_bb), 0, 1) on 16x16
// ============================================================
__global__ __launch_bounds__(256) void finalB_k(const float* __restrict__ aIn,
                                                float* __restrict__ outB)
{
    __shared__ __align__(16) float s_av[1156];     // [4ci][17][17] (in-region, pad-hi)
    __shared__ __align__(16) float s_zv[400];      // [4ci][10][10] (halo 1)
    __shared__ __align__(16) float s_wv[4608];     // [4ci][9tap][32pair][4]

    int tid = threadIdx.x;
    int cq = tid & 15;
    int pb = tid >> 4;
    int pr0 = (pb >> 2) * 2;
    int pc0 = (pb & 3) * 2;
    int tile = blockIdx.x;           // 0..3
    int b    = blockIdx.z;
    int h0 = (tile >> 1) * 8, w0 = (tile & 1) * 8;   // out coords

    unsigned long long accA[2][2], accB[2][2];
    #pragma unroll
    for (int i = 0; i < 2; i++)
        #pragma unroll
        for (int j = 0; j < 2; j++) { accA[i][j] = 0ull; accB[i][j] = 0ull; }

    float2 pw[9];
    float  pa[5];
    float  pz[2];

    auto ld_w = [&](int cc) {
        const float2* src = (const float2*)g_wB + (size_t)cc*2304 + tid;
        #pragma unroll
        for (int k = 0; k < 9; k++) pw[k] = src[k*256];
    };
    auto ld_a = [&](int cc) {
        #pragma unroll
        for (int k = 0; k < 5; k++) {
            int e = tid + k*256;
            float v = 0.f;
            if (e < 1156) {
                int ci = e / 289; int i = e % 289;
                int r = i / 17, c = i % 17;
                int gh = 2*h0 + r, gw = 2*w0 + c;
                if (gh < HH && gw < WW)
                    v = aIn[((size_t)(b*CC + cc*4+ci)*HH + gh)*WW + gw];
            }
            pa[k] = v;
        }
    };
    auto ld_z = [&](int cc) {
        #pragma unroll
        for (int k = 0; k < 2; k++) {
            int e = tid + k*256;
            float v = 0.f;
            if (e < 400) {
                int ci = e / 100; int i = e % 100;
                int r = i / 10, c = i % 10;
                int gh = h0 - 1 + r, gw = w0 - 1 + c;
                if (gh >= 0 && gh < HO && gw >= 0 && gw < WO)
                    v = g_zb[((size_t)(b*CC + cc*4+ci)*HO + gh)*WO + gw];
            }
            pz[k] = v;
        }
    };

    ld_w(0); ld_a(0); ld_z(0);

    for (int cc = 0; cc < 16; cc++) {
        {
            float2* wd = (float2*)s_wv + tid;
            #pragma unroll
            for (int k = 0; k < 9; k++) wd[k*256] = pw[k];
            #pragma unroll
            for (int k = 0; k < 5; k++) {
                int e = tid + k*256;
                if (e < 1156) s_av[e] = pa[k];
            }
            #pragma unroll
            for (int k = 0; k < 2; k++) {
                int e = tid + k*256;
                if (e < 400) s_zv[e] = pz[k];
            }
        }
        __syncthreads();
        if (cc < 15) { ld_w(cc+1); ld_a(cc+1); ld_z(cc+1); }

        #pragma unroll 2
        for (int ci = 0; ci < 4; ci++) {
            #pragma unroll
            for (int kh = 0; kh < 3; kh++) {
                ulonglong2 wa[3], wb[3];
                #pragma unroll
                for (int kw = 0; kw < 3; kw++) {
                    const float* wp = s_wv + ((ci*9 + kh*3+kw)*32 + 2*cq)*4;
                    wa[kw] = *(const ulonglong2*)wp;
                    wb[kw] = *(const ulonglong2*)(wp + 4);
                }
                #pragma unroll
                for (int pr = 0; pr < 2; pr++) {
                    int ra = 2*(pr0 + pr) + kh;      // 0..16
                    int rz = pr0 + pr + kh;          // 0..9
                    unsigned long long va[5], vz[4];
                    #pragma unroll
                    for (int c = 0; c < 5; c++)
                        va[c] = pk2(s_av[ci*289 + ra*17 + 2*pc0 + c]);
                    #pragma unroll
                    for (int c = 0; c < 4; c++)
                        vz[c] = pk2(s_zv[ci*100 + rz*10 + pc0 + c]);
                    #pragma unroll
                    for (int kw = 0; kw < 3; kw++)
                        #pragma unroll
                        for (int px = 0; px < 2; px++) {
                            accA[pr][px] = fma2(wa[kw].x, va[2*px+kw], accA[pr][px]);
                            accA[pr][px] = fma2(wa[kw].y, vz[px+kw],   accA[pr][px]);
                            accB[pr][px] = fma2(wb[kw].x, va[2*px+kw], accB[pr][px]);
                            accB[pr][px] = fma2(wb[kw].y, vz[px+kw],   accB[pr][px]);
                        }
                }
            }
        }
        __syncthreads();
    }

    int co0 = 4 * cq;
    #pragma unroll
    for (int pr = 0; pr < 2; pr++)
        #pragma unroll
        for (int px = 0; px < 2; px++) {
            int h = h0 + pr0 + pr;
            int w = w0 + pc0 + px;
            float lo, hi;
            unpk2(accA[pr][px], lo, hi);
            outB[((b*CC + co0    )*HO + h)*WO + w] = fminf(fmaxf(lo, 0.f), 1.f);
            outB[((b*CC + co0 + 1)*HO + h)*WO + w] = fminf(fmaxf(hi, 0.f), 1.f);
            unpk2(accB[pr][px], lo, hi);
            outB[((b*CC + co0 + 2)*HO + h)*WO + w] = fminf(fmaxf(lo, 0.f), 1.f);
            outB[((b*CC + co0 + 3)*HO + h)*WO + w] = fminf(fmaxf(hi, 0.f), 1.f);
        }
}

// ============================================================
extern "C" void kernel_launch(void* const* d_in, const int* in_sizes, int n_in,
                              void* d_out, int out_size)
{
    (void)in_sizes; (void)n_in; (void)out_size;
    const float* u   = (const float*)d_in[0];
    const float* Win = (const float*)d_in[1];
    const float* Waa = (const float*)d_in[2];
    const float* Wdn = (const float*)d_in[3];
    const float* Wbb = (const float*)d_in[4];
    float* outA = (float*)d_out;                      // a: [16,64,32,32]
    float* outB = outA + BB*CC*HH*WW;                 // b: [16,64,16,16]

    cudaFuncSetAttribute(conv1_k, cudaFuncAttributeMaxDynamicSharedMemorySize, 98304);
    cudaFuncSetAttribute(conv2_k, cudaFuncAttributeMaxDynamicSharedMemorySize, 96768);

    wprep_k<<<864, 256>>>(Win, Waa, Wdn, Wbb);
    ubar_k <<<(BB*CC*HH*WW + 255)/256, 256>>>(u);
    conv1_k<<<dim3(128, 2, BB), 256, 98304>>>(u);
    conv2_k<<<dim3(32, 2, BB), 256, 96768>>>();
    finalA_k<<<dim3(16, 1, BB), 256>>>(outA);
    finalB_k<<<dim3(4, 1, BB), 256>>>(outA, outB);
}

// round 11
// speedup vs baseline: 1.8562x; 1.0436x over previous
#include <cuda_runtime.h>
#include <cstdint>

#define BB 16
#define CC 64
#define HH 32
#define WW 32
#define TT 30
#define TP 32
#define HO 16
#define WO 16

// ---- scratch (static device memory; no allocations) ----
__device__ float g_sf[BB*CC*HH*WW*TP];   // spikes s_a as float (t padded to 32)
__device__ float g_za[BB*CC*HH*WW];
__device__ float g_zb[BB*CC*HO*WO];
__device__ float g_ubar[BB*CC*HH*WW];

// pre-interleaved weights
__device__ __align__(16) float g_wA [16*4608];   // finalA: [cc][ci4][tap9][pair32][4]
__device__ __align__(16) float g_wB [16*4608];   // finalB: same layout (Wdn/Wbb)
__device__ __align__(16) float g_wC1[2*18432];   // conv1:  [cg][(ci*9+tap)*32+co]
__device__ __align__(16) float g_wC2[2*18432];   // conv2:  same (Wdn)

// packed f32x2 helpers
static __device__ __forceinline__ unsigned long long pk2(float x) {
    unsigned long long r;
    asm("mov.b64 %0, {%1, %1};" : "=l"(r) : "f"(x));
    return r;
}
static __device__ __forceinline__ unsigned long long fma2(unsigned long long a,
                                                          unsigned long long b,
                                                          unsigned long long c) {
    unsigned long long d;
    asm("fma.rn.f32x2 %0, %1, %2, %3;" : "=l"(d) : "l"(a), "l"(b), "l"(c));
    return d;
}
static __device__ __forceinline__ void unpk2(unsigned long long v, float& lo, float& hi) {
    asm("mov.b64 {%0, %1}, %2;" : "=f"(lo), "=f"(hi) : "l"(v));
}

// cp.async helpers
static __device__ __forceinline__ void cpa4(unsigned int dst, const void* src, bool ok) {
    asm volatile("cp.async.ca.shared.global [%0], [%1], 4, %2;"
                 :: "r"(dst), "l"(src), "r"(ok ? 4u : 0u));
}
static __device__ __forceinline__ void cpa16(unsigned int dst, const void* src) {
    asm volatile("cp.async.cg.shared.global [%0], [%1], 16;" :: "r"(dst), "l"(src));
}
static __device__ __forceinline__ unsigned int smaddr(const void* p) {
    return (unsigned int)__cvta_generic_to_shared(p);
}
#define CP_COMMIT() asm volatile("cp.async.commit_group;" ::: "memory")

// ============================================================
// weight prep: scatter-read once, so every consumer does coalesced loads
// ============================================================
__global__ __launch_bounds__(256) void wprep_k(const float* __restrict__ Win,
                                               const float* __restrict__ Waa,
                                               const float* __restrict__ Wdn,
                                               const float* __restrict__ Wbb)
{
    int idx = blockIdx.x * 256 + threadIdx.x;
    if (idx < 147456) {                      // g_wA / g_wB (pair-interleaved)
        int half = idx / 73728;              // 0: A, 1: B
        int j = idx % 73728;
        int cc = j / 4608, e = j % 4608;
        int ci = e / 1152, t1 = e % 1152;
        int tap = t1 / 128, t2 = t1 % 128;
        int pair = t2 >> 2, s = t2 & 3;
        int co = pair*2 + (s & 1);
        const float* W;
        if (half == 0) W = (s < 2) ? Win : Waa;
        else           W = (s < 2) ? Wdn : Wbb;
        float v = W[(size_t)co*576 + (cc*4+ci)*9 + tap];
        if (half == 0) g_wA[j] = v; else g_wB[j] = v;
    } else if (idx < 221184) {               // g_wC1 / g_wC2 (conv layouts)
        int j = idx - 147456;
        int half = j / 36864;                // 0: conv1(Win), 1: conv2(Wdn)
        int k = j % 36864;
        int cg = k / 18432, r = k % 18432;
        int ci = r / 288, tap = (r % 288) / 32, co = r & 31;
        const float* W = half ? Wdn : Win;
        float v = W[(size_t)(cg*32+co)*576 + ci*9 + tap];
        if (half == 0) g_wC1[k] = v; else g_wC2[k] = v;
    }
}

// ============================================================
// conv1 + LIF scan A fused. cp.async double-buffered pipeline.
// smem 8448 floats: s_in[2][3072] @0 | s_w[2][1152] @6144 ; reused as transpose
// 16 chunks of 4 ci. Per thread: 2x2 px, 8 co (ty = {pg, cog}).
// ============================================================
__global__ __launch_bounds__(256, 3) void conv1_k(const float* __restrict__ u)
{
    extern __shared__ float sm[];          // 8448 floats

    int tid = threadIdx.x;
    int tx = tid & 31;
    int ty = tid >> 5;
    int pg  = ty >> 2;           // pixel column half (compute)
    int cog = ty & 3;            // co octet (compute)
    int lci = ty & 3;            // staging ci
    int half = ty >> 2;          // staging position half
    int tile = blockIdx.x;       // 0..127
    int cg = blockIdx.y;         // 0..1
    int b  = blockIdx.z;         // 0..15
    int h0 = (tile >> 3) * 2;
    int w0 = (tile & 7) * 4;

    const float* ubase = u + (size_t)(b*CC + lci) * HH*WW*TT;
    const float* wcg = g_wC1 + (size_t)cg * 18432;
    bool tok = (tx < TT);
    int txc = tok ? tx : 0;

    unsigned long long acc[2][2][4];
    #pragma unroll
    for (int i = 0; i < 2; i++)
        #pragma unroll
        for (int j = 0; j < 2; j++)
            #pragma unroll
            for (int k = 0; k < 4; k++) acc[i][j][k] = 0ull;

    auto stage = [&](int cc, int buf) {
        float* si = sm + buf*3072;                 // [ci4][p24][t32]
        float* sw = sm + 6144 + buf*1152;
        const float* up = ubase + (size_t)cc * 4 * HH*WW*TT;
        #pragma unroll
        for (int k = 0; k < 12; k++) {
            int p = half*12 + k;
            int r = p / 6, c = p % 6;
            int gh = h0 - 1 + r, gw = w0 - 1 + c;
            bool ok = tok & (gh >= 0) & (gh < HH) & (gw >= 0) & (gw < WW);
            int ghc = min(max(gh, 0), HH-1);
            int gwc = min(max(gw, 0), WW-1);
            cpa4(smaddr(si + lci*768 + p*32 + tx),
                 up + ((size_t)ghc*WW + gwc)*TT + txc, ok);
        }
        #pragma unroll
        for (int k = 0; k < 2; k++) {
            int e = tid + k*256;
            if (e < 288)
                cpa16(smaddr(sw + e*4), wcg + (size_t)cc*1152 + e*4);
        }
        CP_COMMIT();
    };

    stage(0, 0);

    for (int cc = 0; cc < 16; cc++) {
        if (cc < 15) {
            stage(cc + 1, (cc + 1) & 1);
            asm volatile("cp.async.wait_group 1;" ::: "memory");
        } else {
            asm volatile("cp.async.wait_group 0;" ::: "memory");
        }
        __syncthreads();

        const float* s_ub = sm + (cc & 1)*3072;
        const float* s_wb = sm + 6144 + (cc & 1)*1152;

        #pragma unroll
        for (int ci = 0; ci < 4; ci++) {
            const float* su  = s_ub + ci*768 + (pg*2)*32 + tx;
            const float* swc = s_wb + ci*288 + cog*8;

            unsigned long long ra[4], rb[4];
            #pragma unroll
            for (int c = 0; c < 4; c++) ra[c] = pk2(su[0*192 + c*32]);
            #pragma unroll
            for (int c = 0; c < 4; c++) rb[c] = pk2(su[1*192 + c*32]);

            #pragma unroll
            for (int kh = 0; kh < 3; kh++) {
                ulonglong2 wv0[3], wv1[3];
                #pragma unroll
                for (int kw = 0; kw < 3; kw++) {
                    const float* wp = swc + (kh*3+kw)*32;
                    wv0[kw] = *(const ulonglong2*)wp;
                    wv1[kw] = *(const ulonglong2*)(wp + 4);
                }
                #pragma unroll
                for (int kw = 0; kw < 3; kw++)
                    #pragma unroll
                    for (int pcl = 0; pcl < 2; pcl++) {
                        unsigned long long va = ra[pcl+kw];
                        unsigned long long vb = rb[pcl+kw];
                        acc[0][pcl][0] = fma2(wv0[kw].x, va, acc[0][pcl][0]);
                        acc[0][pcl][1] = fma2(wv0[kw].y, va, acc[0][pcl][1]);
                        acc[0][pcl][2] = fma2(wv1[kw].x, va, acc[0][pcl][2]);
                        acc[0][pcl][3] = fma2(wv1[kw].y, va, acc[0][pcl][3]);
                        acc[1][pcl][0] = fma2(wv0[kw].x, vb, acc[1][pcl][0]);
                        acc[1][pcl][1] = fma2(wv0[kw].y, vb, acc[1][pcl][1]);
                        acc[1][pcl][2] = fma2(wv1[kw].x, vb, acc[1][pcl][2]);
                        acc[1][pcl][3] = fma2(wv1[kw].y, vb, acc[1][pcl][3]);
                    }
                if (kh < 2) {
                    #pragma unroll
                    for (int c = 0; c < 4; c++) {
                        ra[c] = rb[c];
                        rb[c] = pk2(su[(kh+2)*192 + c*32]);
                    }
                }
            }
        }
        __syncthreads();
    }

    // ---- transpose into [copix][t] pitch 33 (aliases whole smem) ----
    #pragma unroll
    for (int pr = 0; pr < 2; pr++)
        #pragma unroll
        for (int pcl = 0; pcl < 2; pcl++)
            #pragma unroll
            for (int k = 0; k < 4; k++) {
                float lo, hi;
                unpk2(acc[pr][pcl][k], lo, hi);
                int px = pr*4 + pg*2 + pcl;
                sm[((cog*8 + 2*k    )*8 + px)*33 + tx] = lo;
                sm[((cog*8 + 2*k + 1)*8 + px)*33 + tx] = hi;
            }
    __syncthreads();

    {
        int co_local = tid >> 3;
        int p = tid & 7;
        int h = h0 + (p >> 2);
        int w = w0 + (p & 3);
        int co = cg*32 + co_local;
        size_t pixIdx = ((size_t)(b*CC + co)*HH + h)*WW + w;

        float out[32];
        float v = 0.f, cnt = 0.f;
        #pragma unroll
        for (int t = 0; t < TT; t++) {
            v = 0.5f * v + sm[tid*33 + t];
            float sp = (v >= 1.0f) ? 1.0f : 0.0f;
            v -= sp;
            cnt += sp;
            out[t] = sp;
        }
        out[30] = 0.f; out[31] = 0.f;
        float4* op = (float4*)&g_sf[pixIdx * TP];
        #pragma unroll
        for (int i = 0; i < 8; i++)
            op[i] = make_float4(out[4*i], out[4*i+1], out[4*i+2], out[4*i+3]);
        g_za[pixIdx] = cnt * (1.0f / 30.0f);
    }
}

// ============================================================
// conv2 (stride-2 SAME: in = 2*out + k) + LIF scan B. cp.async pipeline.
// smem 13824 floats: s_in[2][5760] @0 | s_w[2][1152] @11520 ; transpose aliases
// ============================================================
__global__ __launch_bounds__(256, 3) void conv2_k()
{
    extern __shared__ float sm[];          // 13824 floats

    int tid = threadIdx.x;
    int tx = tid & 31;
    int ty = tid >> 5;
    int pg  = ty >> 2;
    int cog = ty & 3;
    int lci = ty & 3;
    int rg  = ty >> 2;                // 0 -> rows 0..2, 1 -> rows 3..4
    int tile = blockIdx.x;            // 0..31
    int cg = blockIdx.y;
    int b  = blockIdx.z;
    int h0 = (tile >> 2) * 2;         // out coords
    int w0 = (tile & 3) * 4;

    const float* sfbase = g_sf + (size_t)(b*CC + lci) * HH*WW*TP;
    const float* wcg = g_wC2 + (size_t)cg * 18432;

    unsigned long long acc[2][2][4];
    #pragma unroll
    for (int i = 0; i < 2; i++)
        #pragma unroll
        for (int j = 0; j < 2; j++)
            #pragma unroll
            for (int k = 0; k < 4; k++) acc[i][j][k] = 0ull;

    auto stage = [&](int cc, int buf) {
        float* si = sm + buf*5760;               // [ci4][r5][c9][t32]
        float* sw = sm + 11520 + buf*1152;
        const float* up = sfbase + (size_t)cc * 4 * HH*WW*TP;
        #pragma unroll
        for (int rs = 0; rs < 3; rs++) {
            int r = rg*3 + rs;
            if (r < 5) {
                int gh = 2*h0 + r;
                bool hok = (gh < HH);
                int ghc = min(gh, HH-1);
                #pragma unroll
                for (int c = 0; c < 9; c++) {
                    int gw = 2*w0 + c;
                    bool ok = hok & (gw < WW);
                    int gwc = min(gw, WW-1);
                    cpa4(smaddr(si + lci*1440 + r*288 + c*32 + tx),
                         up + ((size_t)ghc*WW + gwc)*TP + tx, ok);
                }
            }
        }
        #pragma unroll
        for (int k = 0; k < 2; k++) {
            int e = tid + k*256;
            if (e < 288)
                cpa16(smaddr(sw + e*4), wcg + (size_t)cc*1152 + e*4);
        }
        CP_COMMIT();
    };

    stage(0, 0);

    for (int cc = 0; cc < 16; cc++) {
        if (cc < 15) {
            stage(cc + 1, (cc + 1) & 1);
            asm volatile("cp.async.wait_group 1;" ::: "memory");
        } else {
            asm volatile("cp.async.wait_group 0;" ::: "memory");
        }
        __syncthreads();

        const float* s_ub = sm + (cc & 1)*5760;
        const float* s_wb = sm + 11520 + (cc & 1)*1152;

        #pragma unroll
        for (int ci = 0; ci < 4; ci++) {
            const float* su  = s_ub + ci*1440 + (pg*4)*32 + tx;
            const float* swc = s_wb + ci*288 + cog*8;

            #pragma unroll
            for (int kh = 0; kh < 3; kh++) {
                ulonglong2 wv0[3], wv1[3];
                #pragma unroll
                for (int kw = 0; kw < 3; kw++) {
                    const float* wp = swc + (kh*3+kw)*32;
                    wv0[kw] = *(const ulonglong2*)wp;
                    wv1[kw] = *(const ulonglong2*)(wp + 4);
                }
                #pragma unroll
                for (int pr = 0; pr < 2; pr++) {
                    int r = 2*pr + kh;
                    unsigned long long vd[5];
                    #pragma unroll
                    for (int c = 0; c < 5; c++)
                        vd[c] = pk2(su[r*288 + c*32]);
                    #pragma unroll
                    for (int kw = 0; kw < 3; kw++)
                        #pragma unroll
                        for (int pcl = 0; pcl < 2; pcl++) {
                            unsigned long long v = vd[2*pcl + kw];
                            acc[pr][pcl][0] = fma2(wv0[kw].x, v, acc[pr][pcl][0]);
                            acc[pr][pcl][1] = fma2(wv0[kw].y, v, acc[pr][pcl][1]);
                            acc[pr][pcl][2] = fma2(wv1[kw].x, v, acc[pr][pcl][2]);
                            acc[pr][pcl][3] = fma2(wv1[kw].y, v, acc[pr][pcl][3]);
                        }
                }
            }
        }
        __syncthreads();
    }

    // ---- transpose (aliases smem) + scan B ----
    #pragma unroll
    for (int pr = 0; pr < 2; pr++)
        #pragma unroll
        for (int pcl = 0; pcl < 2; pcl++)
            #pragma unroll
            for (int k = 0; k < 4; k++) {
                float lo, hi;
                unpk2(acc[pr][pcl][k], lo, hi);
                int px = pr*4 + pg*2 + pcl;
                sm[((cog*8 + 2*k    )*8 + px)*33 + tx] = lo;
                sm[((cog*8 + 2*k + 1)*8 + px)*33 + tx] = hi;
            }
    __syncthreads();
    {
        int co_local = tid >> 3;
        int p = tid & 7;
        int h = h0 + (p >> 2);
        int w = w0 + (p & 3);
        int co = cg*32 + co_local;
        float v = 0.f, cnt = 0.f;
        #pragma unroll
        for (int t = 0; t < TT; t++) {
            v = 0.5f * v + sm[tid*33 + t];
            float sp = (v >= 1.0f) ? 1.0f : 0.0f;
            v -= sp;
            cnt += sp;
        }
        g_zb[((size_t)(b*CC + co)*HO + h)*WO + w] = cnt * (1.0f / 30.0f);
    }
}

// ============================================================
// u_bar: leaky temporal average (float2 loads)
// ============================================================
__global__ __launch_bounds__(256) void ubar_k(const float* __restrict__ u)
{
    int pix = blockIdx.x * blockDim.x + threadIdx.x;
    if (pix >= BB*CC*HH*WW) return;
    const float2* up2 = (const float2*)(u + (size_t)pix * TT);
    float uu[30];
    #pragma unroll
    for (int i = 0; i < 15; i++) {
        float2 v = up2[i];
        uu[2*i] = v.x; uu[2*i+1] = v.y;
    }
    float p = 1.0f;
    #pragma unroll
    for (int i = 0; i < 30; i++) p *= 0.9f;      // 0.9^30
    float p31 = p * 0.9f;
    float inv = 0.1f / (1.0f - p31);
    float acc = (1.0f + p) * uu[29];
    float w = 0.9f;
    #pragma unroll
    for (int j = 28; j >= 0; j--) {
        acc += w * uu[j];
        w *= 0.9f;
    }
    g_ubar[pix] = acc * inv;
}

// ============================================================
// final A: a = clip(conv(u_bar,W_in) + conv(z_a,W_aa), 0, 1)
// ============================================================
__global__ __launch_bounds__(256) void finalA_k(float* __restrict__ outA)
{
    __shared__ __align__(16) float s_ubv[400];     // [4ci][10][10]
    __shared__ __align__(16) float s_zav[400];
    __shared__ __align__(16) float s_wv[4608];     // [4ci][9tap][32pair][4]

    int tid = threadIdx.x;
    int cq = tid & 15;
    int pb = tid >> 4;
    int pr0 = (pb >> 2) * 2;
    int pc0 = (pb & 3) * 2;
    int tile = blockIdx.x;           // 0..15
    int b    = blockIdx.z;
    int h0 = (tile >> 2) * 8, w0 = (tile & 3) * 8;

    unsigned long long accA[2][2], accB[2][2];
    #pragma unroll
    for (int i = 0; i < 2; i++)
        #pragma unroll
        for (int j = 0; j < 2; j++) { accA[i][j] = 0ull; accB[i][j] = 0ull; }

    float2 pw[9];
    float  pv[4];

    auto ld_w = [&](int cc) {
        const float2* src = (const float2*)g_wA + (size_t)cc*2304 + tid;
        #pragma unroll
        for (int k = 0; k < 9; k++) pw[k] = src[k*256];
    };
    auto ld_v = [&](int cc) {
        #pragma unroll
        for (int k = 0; k < 4; k++) {
            int e = tid + k*256;
            float v = 0.f;
            if (e < 800) {
                int a = (e >= 400);
                int i = e - a*400;
                int ci = i / 100; int rem = i % 100;
                int r = rem / 10, c = rem % 10;
                int gh = h0 - 1 + r, gw = w0 - 1 + c;
                if (gh >= 0 && gh < HH && gw >= 0 && gw < WW) {
                    size_t gi = ((size_t)(b*CC + cc*4+ci)*HH + gh)*WW + gw;
                    v = a ? g_za[gi] : g_ubar[gi];
                }
            }
            pv[k] = v;
        }
    };

    ld_w(0); ld_v(0);

    for (int cc = 0; cc < 16; cc++) {
        {
            float2* wd = (float2*)s_wv + tid;
            #pragma unroll
            for (int k = 0; k < 9; k++) wd[k*256] = pw[k];
            #pragma unroll
            for (int k = 0; k < 4; k++) {
                int e = tid + k*256;
                if (e < 800) {
                    if (e >= 400) s_zav[e-400] = pv[k];
                    else          s_ubv[e]     = pv[k];
                }
            }
        }
        __syncthreads();
        if (cc < 15) { ld_w(cc+1); ld_v(cc+1); }

        #pragma unroll 2
        for (int ci = 0; ci < 4; ci++) {
            unsigned long long ua[4], ub[4], za[4], zb[4];
            #pragma unroll
            for (int c = 0; c < 4; c++) {
                ua[c] = pk2(s_ubv[ci*100 + (pr0  )*10 + pc0 + c]);
                za[c] = pk2(s_zav[ci*100 + (pr0  )*10 + pc0 + c]);
                ub[c] = pk2(s_ubv[ci*100 + (pr0+1)*10 + pc0 + c]);
                zb[c] = pk2(s_zav[ci*100 + (pr0+1)*10 + pc0 + c]);
            }
            #pragma unroll
            for (int kh = 0; kh < 3; kh++) {
                ulonglong2 wa[3], wb[3];
                #pragma unroll
                for (int kw = 0; kw < 3; kw++) {
                    const float* wp = s_wv + ((ci*9 + kh*3+kw)*32 + 2*cq)*4;
                    wa[kw] = *(const ulonglong2*)wp;
                    wb[kw] = *(const ulonglong2*)(wp + 4);
                }
                #pragma unroll
                for (int kw = 0; kw < 3; kw++)
                    #pragma unroll
                    for (int px = 0; px < 2; px++) {
                        accA[0][px] = fma2(wa[kw].x, ua[px+kw], accA[0][px]);
                        accA[0][px] = fma2(wa[kw].y, za[px+kw], accA[0][px]);
                        accB[0][px] = fma2(wb[kw].x, ua[px+kw], accB[0][px]);
                        accB[0][px] = fma2(wb[kw].y, za[px+kw], accB[0][px]);
                        accA[1][px] = fma2(wa[kw].x, ub[px+kw], accA[1][px]);
                        accA[1][px] = fma2(wa[kw].y, zb[px+kw], accA[1][px]);
                        accB[1][px] = fma2(wb[kw].x, ub[px+kw], accB[1][px]);
                        accB[1][px] = fma2(wb[kw].y, zb[px+kw], accB[1][px]);
                    }
                if (kh < 2) {
                    #pragma unroll
                    for (int c = 0; c < 4; c++) {
                        ua[c] = ub[c]; za[c] = zb[c];
                        ub[c] = pk2(s_ubv[ci*100 + (pr0+kh+2)*10 + pc0 + c]);
                        zb[c] = pk2(s_zav[ci*100 + (pr0+kh+2)*10 + pc0 + c]);
                    }
                }
            }
        }
        __syncthreads();
    }

    int co0 = 4 * cq;
    #pragma unroll
    for (int pr = 0; pr < 2; pr++)
        #pragma unroll
        for (int px = 0; px < 2; px++) {
            int h = h0 + pr0 + pr;
            int w = w0 + pc0 + px;
            float lo, hi;
            unpk2(accA[pr][px], lo, hi);
            outA[((b*CC + co0    )*HH + h)*WW + w] = fminf(fmaxf(lo, 0.f), 1.f);
            outA[((b*CC + co0 + 1)*HH + h)*WW + w] = fminf(fmaxf(hi, 0.f), 1.f);
            unpk2(accB[pr][px], lo, hi);
            outA[((b*CC + co0 + 2)*HH + h)*WW + w] = fminf(fmaxf(lo, 0.f), 1.f);
            outA[((b*CC + co0 + 3)*HH + h)*WW + w] = fminf(fmaxf(hi, 0.f), 1.f);
        }
}

// ============================================================
// final B: b_out = clip(conv(a,W_down,s2) + conv(z_b,W_bb), 0, 1) on 16x16
// ============================================================
__global__ __launch_bounds__(256) void finalB_k(const float* __restrict__ aIn,
                                                float* __restrict__ outB)
{
    __shared__ __align__(16) float s_av[1156];     // [4ci][17][17]
    __shared__ __align__(16) float s_zv[400];      // [4ci][10][10]
    __shared__ __align__(16) float s_wv[4608];

    int tid = threadIdx.x;
    int cq = tid & 15;
    int pb = tid >> 4;
    int pr0 = (pb >> 2) * 2;
    int pc0 = (pb & 3) * 2;
    int tile = blockIdx.x;           // 0..3
    int b    = blockIdx.z;
    int h0 = (tile >> 1) * 8, w0 = (tile & 1) * 8;   // out coords

    unsigned long long accA[2][2], accB[2][2];
    #pragma unroll
    for (int i = 0; i < 2; i++)
        #pragma unroll
        for (int j = 0; j < 2; j++) { accA[i][j] = 0ull; accB[i][j] = 0ull; }

    float2 pw[9];
    float  pa[5];
    float  pz[2];

    auto ld_w = [&](int cc) {
        const float2* src = (const float2*)g_wB + (size_t)cc*2304 + tid;
        #pragma unroll
        for (int k = 0; k < 9; k++) pw[k] = src[k*256];
    };
    auto ld_a = [&](int cc) {
        #pragma unroll
        for (int k = 0; k < 5; k++) {
            int e = tid + k*256;
            float v = 0.f;
            if (e < 1156) {
                int ci = e / 289; int i = e % 289;
                int r = i / 17, c = i % 17;
                int gh = 2*h0 + r, gw = 2*w0 + c;
                if (gh < HH && gw < WW)
                    v = aIn[((size_t)(b*CC + cc*4+ci)*HH + gh)*WW + gw];
            }
            pa[k] = v;
        }
    };
    auto ld_z = [&](int cc) {
        #pragma unroll
        for (int k = 0; k < 2; k++) {
            int e = tid + k*256;
            float v = 0.f;
            if (e < 400) {
                int ci = e / 100; int i = e % 100;
                int r = i / 10, c = i % 10;
                int gh = h0 - 1 + r, gw = w0 - 1 + c;
                if (gh >= 0 && gh < HO && gw >= 0 && gw < WO)
                    v = g_zb[((size_t)(b*CC + cc*4+ci)*HO + gh)*WO + gw];
            }
            pz[k] = v;
        }
    };

    ld_w(0); ld_a(0); ld_z(0);

    for (int cc = 0; cc < 16; cc++) {
        {
            float2* wd = (float2*)s_wv + tid;
            #pragma unroll
            for (int k = 0; k < 9; k++) wd[k*256] = pw[k];
            #pragma unroll
            for (int k = 0; k < 5; k++) {
                int e = tid + k*256;
                if (e < 1156) s_av[e] = pa[k];
            }
            #pragma unroll
            for (int k = 0; k < 2; k++) {
                int e = tid + k*256;
                if (e < 400) s_zv[e] = pz[k];
            }
        }
        __syncthreads();
        if (cc < 15) { ld_w(cc+1); ld_a(cc+1); ld_z(cc+1); }

        #pragma unroll 2
        for (int ci = 0; ci < 4; ci++) {
            #pragma unroll
            for (int kh = 0; kh < 3; kh++) {
                ulonglong2 wa[3], wb[3];
                #pragma unroll
                for (int kw = 0; kw < 3; kw++) {
                    const float* wp = s_wv + ((ci*9 + kh*3+kw)*32 + 2*cq)*4;
                    wa[kw] = *(const ulonglong2*)wp;
                    wb[kw] = *(const ulonglong2*)(wp + 4);
                }
                #pragma unroll
                for (int pr = 0; pr < 2; pr++) {
                    int ra = 2*(pr0 + pr) + kh;      // 0..16
                    int rz = pr0 + pr + kh;          // 0..9
                    unsigned long long va[5], vz[4];
                    #pragma unroll
                    for (int c = 0; c < 5; c++)
                        va[c] = pk2(s_av[ci*289 + ra*17 + 2*pc0 + c]);
                    #pragma unroll
                    for (int c = 0; c < 4; c++)
                        vz[c] = pk2(s_zv[ci*100 + rz*10 + pc0 + c]);
                    #pragma unroll
                    for (int kw = 0; kw < 3; kw++)
                        #pragma unroll
                        for (int px = 0; px < 2; px++) {
                            accA[pr][px] = fma2(wa[kw].x, va[2*px+kw], accA[pr][px]);
                            accA[pr][px] = fma2(wa[kw].y, vz[px+kw],   accA[pr][px]);
                            accB[pr][px] = fma2(wb[kw].x, va[2*px+kw], accB[pr][px]);
                            accB[pr][px] = fma2(wb[kw].y, vz[px+kw],   accB[pr][px]);
                        }
                }
            }
        }
        __syncthreads();
    }

    int co0 = 4 * cq;
    #pragma unroll
    for (int pr = 0; pr < 2; pr++)
        #pragma unroll
        for (int px = 0; px < 2; px++) {
            int h = h0 + pr0 + pr;
            int w = w0 + pc0 + px;
            float lo, hi;
            unpk2(accA[pr][px], lo, hi);
            outB[((b*CC + co0    )*HO + h)*WO + w] = fminf(fmaxf(lo, 0.f), 1.f);
            outB[((b*CC + co0 + 1)*HO + h)*WO + w] = fminf(fmaxf(hi, 0.f), 1.f);
            unpk2(accB[pr][px], lo, hi);
            outB[((b*CC + co0 + 2)*HO + h)*WO + w] = fminf(fmaxf(lo, 0.f), 1.f);
            outB[((b*CC + co0 + 3)*HO + h)*WO + w] = fminf(fmaxf(hi, 0.f), 1.f);
        }
}

// ============================================================
extern "C" void kernel_launch(void* const* d_in, const int* in_sizes, int n_in,
                              void* d_out, int out_size)
{
    (void)in_sizes; (void)n_in; (void)out_size;
    const float* u   = (const float*)d_in[0];
    const float* Win = (const float*)d_in[1];
    const float* Waa = (const float*)d_in[2];
    const float* Wdn = (const float*)d_in[3];
    const float* Wbb = (const float*)d_in[4];
    float* outA = (float*)d_out;                      // a: [16,64,32,32]
    float* outB = outA + BB*CC*HH*WW;                 // b: [16,64,16,16]

    cudaFuncSetAttribute(conv1_k, cudaFuncAttributeMaxDynamicSharedMemorySize, 33792);
    cudaFuncSetAttribute(conv2_k, cudaFuncAttributeMaxDynamicSharedMemorySize, 55296);

    wprep_k<<<864, 256>>>(Win, Waa, Wdn, Wbb);
    ubar_k <<<(BB*CC*HH*WW + 255)/256, 256>>>(u);
    conv1_k<<<dim3(128, 2, BB), 256, 33792>>>(u);
    conv2_k<<<dim3(32, 2, BB), 256, 55296>>>();
    finalA_k<<<dim3(16, 1, BB), 256>>>(outA);
    finalB_k<<<dim3(4, 1, BB), 256>>>(outA, outB);
}

// round 13
// speedup vs baseline: 1.8951x; 1.0210x over previous
#include <cuda_runtime.h>
#include <cstdint>

#define BB 16
#define CC 64
#define HH 32
#define WW 32
#define TT 30
#define TP 32
#define HO 16
#define WO 16

// ---- scratch (static device memory; no allocations) ----
__device__ float g_sf[BB*CC*HH*WW*TP];   // spikes s_a as float (t padded to 32)
__device__ float g_za[BB*CC*HH*WW];
__device__ float g_zb[BB*CC*HO*WO];
__device__ float g_ubar[BB*CC*HH*WW];

// pre-interleaved weights
__device__ __align__(16) float g_wA [16*4608];   // finalA: [cc][ci4][tap9][pair32][4]
__device__ __align__(16) float g_wB [16*4608];   // finalB: same layout (Wdn/Wbb)
__device__ __align__(16) float g_wC1[2*18432];   // conv1:  [cg][(ci*9+tap)*32+co]
__device__ __align__(16) float g_wC2[2*18432];   // conv2:  same (Wdn)

// packed f32x2 helpers
static __device__ __forceinline__ unsigned long long pk2(float x) {
    unsigned long long r;
    asm("mov.b64 %0, {%1, %1};" : "=l"(r) : "f"(x));
    return r;
}
static __device__ __forceinline__ unsigned long long fma2(unsigned long long a,
                                                          unsigned long long b,
                                                          unsigned long long c) {
    unsigned long long d;
    asm("fma.rn.f32x2 %0, %1, %2, %3;" : "=l"(d) : "l"(a), "l"(b), "l"(c));
    return d;
}
static __device__ __forceinline__ void unpk2(unsigned long long v, float& lo, float& hi) {
    asm("mov.b64 {%0, %1}, %2;" : "=f"(lo), "=f"(hi) : "l"(v));
}

// cp.async helpers
static __device__ __forceinline__ void cpa4(unsigned int dst, const void* src, bool ok) {
    asm volatile("cp.async.ca.shared.global [%0], [%1], 4, %2;"
                 :: "r"(dst), "l"(src), "r"(ok ? 4u : 0u));
}
static __device__ __forceinline__ void cpa16(unsigned int dst, const void* src) {
    asm volatile("cp.async.cg.shared.global [%0], [%1], 16;" :: "r"(dst), "l"(src));
}
static __device__ __forceinline__ unsigned int smaddr(const void* p) {
    return (unsigned int)__cvta_generic_to_shared(p);
}
#define CP_COMMIT() asm volatile("cp.async.commit_group;" ::: "memory")

// ============================================================
// weight prep: scatter-read once, so every consumer does coalesced loads
// ============================================================
__global__ __launch_bounds__(256) void wprep_k(const float* __restrict__ Win,
                                               const float* __restrict__ Waa,
                                               const float* __restrict__ Wdn,
                                               const float* __restrict__ Wbb)
{
    int idx = blockIdx.x * 256 + threadIdx.x;
    if (idx < 147456) {                      // g_wA / g_wB (pair-interleaved)
        int half = idx / 73728;              // 0: A, 1: B
        int j = idx % 73728;
        int cc = j / 4608, e = j % 4608;
        int ci = e / 1152, t1 = e % 1152;
        int tap = t1 / 128, t2 = t1 % 128;
        int pair = t2 >> 2, s = t2 & 3;
        int co = pair*2 + (s & 1);
        const float* W;
        if (half == 0) W = (s < 2) ? Win : Waa;
        else           W = (s < 2) ? Wdn : Wbb;
        float v = W[(size_t)co*576 + (cc*4+ci)*9 + tap];
        if (half == 0) g_wA[j] = v; else g_wB[j] = v;
    } else if (idx < 221184) {               // g_wC1 / g_wC2 (conv layouts)
        int j = idx - 147456;
        int half = j / 36864;                // 0: conv1(Win), 1: conv2(Wdn)
        int k = j % 36864;
        int cg = k / 18432, r = k % 18432;
        int ci = r / 288, tap = (r % 288) / 32, co = r & 31;
        const float* W = half ? Wdn : Win;
        float v = W[(size_t)(cg*32+co)*576 + ci*9 + tap];
        if (half == 0) g_wC1[k] = v; else g_wC2[k] = v;
    }
}

// ============================================================
// conv1 + LIF scan A fused. cp.async double-buffered, 8 chunks of 8 ci.
// smem 16896 floats: s_in[2][6144] @0 | s_w[2][2304] @12288 ; transpose aliases
// Per thread: 2x2 px, 8 co (ty = {pg, cog}); staging ci = ty.
// ============================================================
__global__ __launch_bounds__(256, 3) void conv1_k(const float* __restrict__ u)
{
    extern __shared__ float sm[];          // 16896 floats

    int tid = threadIdx.x;
    int tx = tid & 31;
    int ty = tid >> 5;
    int pg  = ty >> 2;           // pixel column half (compute)
    int cog = ty & 3;            // co octet (compute)
    int tile = blockIdx.x;       // 0..127
    int cg = blockIdx.y;         // 0..1
    int b  = blockIdx.z;         // 0..15
    int h0 = (tile >> 3) * 2;
    int w0 = (tile & 7) * 4;

    const float* ubase = u + (size_t)(b*CC + ty) * HH*WW*TT;   // staging ci = ty
    const float* wcg = g_wC1 + (size_t)cg * 18432;
    bool tok = (tx < TT);
    int txc = tok ? tx : 0;

    unsigned long long acc[2][2][4];
    #pragma unroll
    for (int i = 0; i < 2; i++)
        #pragma unroll
        for (int j = 0; j < 2; j++)
            #pragma unroll
            for (int k = 0; k < 4; k++) acc[i][j][k] = 0ull;

    auto stage = [&](int cc, int buf) {
        float* si = sm + buf*6144;                 // [ci8][p24][t32]
        float* sw = sm + 12288 + buf*2304;
        const float* up = ubase + (size_t)cc * 8 * HH*WW*TT;
        #pragma unroll
        for (int p = 0; p < 24; p++) {
            int r = p / 6, c = p % 6;
            int gh = h0 - 1 + r, gw = w0 - 1 + c;
            bool ok = tok & (gh >= 0) & (gh < HH) & (gw >= 0) & (gw < WW);
            int ghc = min(max(gh, 0), HH-1);
            int gwc = min(max(gw, 0), WW-1);
            cpa4(smaddr(si + ty*768 + p*32 + tx),
                 up + ((size_t)ghc*WW + gwc)*TT + txc, ok);
        }
        #pragma unroll
        for (int k = 0; k < 3; k++) {
            int e = tid + k*256;
            if (e < 576)
                cpa16(smaddr(sw + e*4), wcg + (size_t)cc*2304 + e*4);
        }
        CP_COMMIT();
    };

    stage(0, 0);

    for (int cc = 0; cc < 8; cc++) {
        if (cc < 7) {
            stage(cc + 1, (cc + 1) & 1);
            asm volatile("cp.async.wait_group 1;" ::: "memory");
        } else {
            asm volatile("cp.async.wait_group 0;" ::: "memory");
        }
        __syncthreads();

        const float* s_ub = sm + (cc & 1)*6144;
        const float* s_wb = sm + 12288 + (cc & 1)*2304;

        #pragma unroll 2
        for (int ci = 0; ci < 8; ci++) {
            const float* su  = s_ub + ci*768 + (pg*2)*32 + tx;
            const float* swc = s_wb + ci*288 + cog*8;

            unsigned long long ra[4], rb[4];
            #pragma unroll
            for (int c = 0; c < 4; c++) ra[c] = pk2(su[0*192 + c*32]);
            #pragma unroll
            for (int c = 0; c < 4; c++) rb[c] = pk2(su[1*192 + c*32]);

            #pragma unroll
            for (int kh = 0; kh < 3; kh++) {
                ulonglong2 wv0[3], wv1[3];
                #pragma unroll
                for (int kw = 0; kw < 3; kw++) {
                    const float* wp = swc + (kh*3+kw)*32;
                    wv0[kw] = *(const ulonglong2*)wp;
                    wv1[kw] = *(const ulonglong2*)(wp + 4);
                }
                #pragma unroll
                for (int kw = 0; kw < 3; kw++)
                    #pragma unroll
                    for (int pcl = 0; pcl < 2; pcl++) {
                        unsigned long long va = ra[pcl+kw];
                        unsigned long long vb = rb[pcl+kw];
                        acc[0][pcl][0] = fma2(wv0[kw].x, va, acc[0][pcl][0]);
                        acc[0][pcl][1] = fma2(wv0[kw].y, va, acc[0][pcl][1]);
                        acc[0][pcl][2] = fma2(wv1[kw].x, va, acc[0][pcl][2]);
                        acc[0][pcl][3] = fma2(wv1[kw].y, va, acc[0][pcl][3]);
                        acc[1][pcl][0] = fma2(wv0[kw].x, vb, acc[1][pcl][0]);
                        acc[1][pcl][1] = fma2(wv0[kw].y, vb, acc[1][pcl][1]);
                        acc[1][pcl][2] = fma2(wv1[kw].x, vb, acc[1][pcl][2]);
                        acc[1][pcl][3] = fma2(wv1[kw].y, vb, acc[1][pcl][3]);
                    }
                if (kh < 2) {
                    #pragma unroll
                    for (int c = 0; c < 4; c++) {
                        ra[c] = rb[c];
                        rb[c] = pk2(su[(kh+2)*192 + c*32]);
                    }
                }
            }
        }
        __syncthreads();
    }

    // ---- transpose into [copix][t] pitch 33 (aliases whole smem) ----
    #pragma unroll
    for (int pr = 0; pr < 2; pr++)
        #pragma unroll
        for (int pcl = 0; pcl < 2; pcl++)
            #pragma unroll
            for (int k = 0; k < 4; k++) {
                float lo, hi;
                unpk2(acc[pr][pcl][k], lo, hi);
                int px = pr*4 + pg*2 + pcl;
                sm[((cog*8 + 2*k    )*8 + px)*33 + tx] = lo;
                sm[((cog*8 + 2*k + 1)*8 + px)*33 + tx] = hi;
            }
    __syncthreads();

    {
        int co_local = tid >> 3;
        int p = tid & 7;
        int h = h0 + (p >> 2);
        int w = w0 + (p & 3);
        int co = cg*32 + co_local;
        size_t pixIdx = ((size_t)(b*CC + co)*HH + h)*WW + w;

        float out[32];
        float v = 0.f, cnt = 0.f;
        #pragma unroll
        for (int t = 0; t < TT; t++) {
            v = 0.5f * v + sm[tid*33 + t];
            float sp = (v >= 1.0f) ? 1.0f : 0.0f;
            v -= sp;
            cnt += sp;
            out[t] = sp;
        }
        out[30] = 0.f; out[31] = 0.f;
        float4* op = (float4*)&g_sf[pixIdx * TP];
        #pragma unroll
        for (int i = 0; i < 8; i++)
            op[i] = make_float4(out[4*i], out[4*i+1], out[4*i+2], out[4*i+3]);
        g_za[pixIdx] = cnt * (1.0f / 30.0f);
    }
}

// ============================================================
// conv2 (stride-2 SAME: in = 2*out + k) + LIF scan B. cp.async pipeline.
// smem 13824 floats: s_in[2][5760] @0 | s_w[2][1152] @11520 ; transpose aliases
// ============================================================
__global__ __launch_bounds__(256, 3) void conv2_k()
{
    extern __shared__ float sm[];          // 13824 floats

    int tid = threadIdx.x;
    int tx = tid & 31;
    int ty = tid >> 5;
    int pg  = ty >> 2;
    int cog = ty & 3;
    int lci = ty & 3;
    int rg  = ty >> 2;                // 0 -> rows 0..2, 1 -> rows 3..4
    int tile = blockIdx.x;            // 0..31
    int cg = blockIdx.y;
    int b  = blockIdx.z;
    int h0 = (tile >> 2) * 2;         // out coords
    int w0 = (tile & 3) * 4;

    const float* sfbase = g_sf + (size_t)(b*CC + lci) * HH*WW*TP;
    const float* wcg = g_wC2 + (size_t)cg * 18432;

    unsigned long long acc[2][2][4];
    #pragma unroll
    for (int i = 0; i < 2; i++)
        #pragma unroll
        for (int j = 0; j < 2; j++)
            #pragma unroll
            for (int k = 0; k < 4; k++) acc[i][j][k] = 0ull;

    auto stage = [&](int cc, int buf) {
        float* si = sm + buf*5760;               // [ci4][r5][c9][t32]
        float* sw = sm + 11520 + buf*1152;
        const float* up = sfbase + (size_t)cc * 4 * HH*WW*TP;
        #pragma unroll
        for (int rs = 0; rs < 3; rs++) {
            int r = rg*3 + rs;
            if (r < 5) {
                int gh = 2*h0 + r;
                bool hok = (gh < HH);
                int ghc = min(gh, HH-1);
                #pragma unroll
                for (int c = 0; c < 9; c++) {
                    int gw = 2*w0 + c;
                    bool ok = hok & (gw < WW);
                    int gwc = min(gw, WW-1);
                    cpa4(smaddr(si + lci*1440 + r*288 + c*32 + tx),
                         up + ((size_t)ghc*WW + gwc)*TP + tx, ok);
                }
            }
        }
        #pragma unroll
        for (int k = 0; k < 2; k++) {
            int e = tid + k*256;
            if (e < 288)
                cpa16(smaddr(sw + e*4), wcg + (size_t)cc*1152 + e*4);
        }
        CP_COMMIT();
    };

    stage(0, 0);

    for (int cc = 0; cc < 16; cc++) {
        if (cc < 15) {
            stage(cc + 1, (cc + 1) & 1);
            asm volatile("cp.async.wait_group 1;" ::: "memory");
        } else {
            asm volatile("cp.async.wait_group 0;" ::: "memory");
        }
        __syncthreads();

        const float* s_ub = sm + (cc & 1)*5760;
        const float* s_wb = sm + 11520 + (cc & 1)*1152;

        #pragma unroll
        for (int ci = 0; ci < 4; ci++) {
            const float* su  = s_ub + ci*1440 + (pg*4)*32 + tx;
            const float* swc = s_wb + ci*288 + cog*8;

            #pragma unroll
            for (int kh = 0; kh < 3; kh++) {
                ulonglong2 wv0[3], wv1[3];
                #pragma unroll
                for (int kw = 0; kw < 3; kw++) {
                    const float* wp = swc + (kh*3+kw)*32;
                    wv0[kw] = *(const ulonglong2*)wp;
                    wv1[kw] = *(const ulonglong2*)(wp + 4);
                }
                #pragma unroll
                for (int pr = 0; pr < 2; pr++) {
                    int r = 2*pr + kh;
                    unsigned long long vd[5];
                    #pragma unroll
                    for (int c = 0; c < 5; c++)
                        vd[c] = pk2(su[r*288 + c*32]);
                    #pragma unroll
                    for (int kw = 0; kw < 3; kw++)
                        #pragma unroll
                        for (int pcl = 0; pcl < 2; pcl++) {
                            unsigned long long v = vd[2*pcl + kw];
                            acc[pr][pcl][0] = fma2(wv0[kw].x, v, acc[pr][pcl][0]);
                            acc[pr][pcl][1] = fma2(wv0[kw].y, v, acc[pr][pcl][1]);
                            acc[pr][pcl][2] = fma2(wv1[kw].x, v, acc[pr][pcl][2]);
                            acc[pr][pcl][3] = fma2(wv1[kw].y, v, acc[pr][pcl][3]);
                        }
                }
            }
        }
        __syncthreads();
    }

    // ---- transpose (aliases smem) + scan B ----
    #pragma unroll
    for (int pr = 0; pr < 2; pr++)
        #pragma unroll
        for (int pcl = 0; pcl < 2; pcl++)
            #pragma unroll
            for (int k = 0; k < 4; k++) {
                float lo, hi;
                unpk2(acc[pr][pcl][k], lo, hi);
                int px = pr*4 + pg*2 + pcl;
                sm[((cog*8 + 2*k    )*8 + px)*33 + tx] = lo;
                sm[((cog*8 + 2*k + 1)*8 + px)*33 + tx] = hi;
            }
    __syncthreads();
    {
        int co_local = tid >> 3;
        int p = tid & 7;
        int h = h0 + (p >> 2);
        int w = w0 + (p & 3);
        int co = cg*32 + co_local;
        float v = 0.f, cnt = 0.f;
        #pragma unroll
        for (int t = 0; t < TT; t++) {
            v = 0.5f * v + sm[tid*33 + t];
            float sp = (v >= 1.0f) ? 1.0f : 0.0f;
            v -= sp;
            cnt += sp;
        }
        g_zb[((size_t)(b*CC + co)*HO + h)*WO + w] = cnt * (1.0f / 30.0f);
    }
}

// ============================================================
// u_bar: leaky temporal average (float2 loads)
// ============================================================
__global__ __launch_bounds__(256) void ubar_k(const float* __restrict__ u)
{
    int pix = blockIdx.x * blockDim.x + threadIdx.x;
    if (pix >= BB*CC*HH*WW) return;
    const float2* up2 = (const float2*)(u + (size_t)pix * TT);
    float uu[30];
    #pragma unroll
    for (int i = 0; i < 15; i++) {
        float2 v = up2[i];
        uu[2*i] = v.x; uu[2*i+1] = v.y;
    }
    float p = 1.0f;
    #pragma unroll
    for (int i = 0; i < 30; i++) p *= 0.9f;      // 0.9^30
    float p31 = p * 0.9f;
    float inv = 0.1f / (1.0f - p31);
    float acc = (1.0f + p) * uu[29];
    float w = 0.9f;
    #pragma unroll
    for (int j = 28; j >= 0; j--) {
        acc += w * uu[j];
        w *= 0.9f;
    }
    g_ubar[pix] = acc * inv;
}

// ============================================================
// final A: a = clip(conv(u_bar,W_in) + conv(z_a,W_aa), 0, 1)
// 512 blocks: 32 tiles (4x8 px) x 16 b. thread: pair=tid&31 (2 co), pb=tid>>5 (2x2 px)
// one LDS.128 per tap = {Win pair, Waa pair}. High occupancy (~19KB smem).
// ============================================================
__global__ __launch_bounds__(256) void finalA_k(float* __restrict__ outA)
{
    __shared__ __align__(16) float s_ubv[240];     // [4ci][6][10]
    __shared__ __align__(16) float s_zav[240];
    __shared__ __align__(16) float s_wv[4608];     // [4ci][9tap][32pair][4]

    int tid = threadIdx.x;
    int pairI = tid & 31;
    int pb = tid >> 5;               // 0..7
    int pr0 = (pb >> 2) * 2;         // 0 or 2
    int pc0 = (pb & 3) * 2;          // 0,2,4,6
    int tile = blockIdx.x;           // 0..31
    int b    = blockIdx.z;
    int h0 = (tile >> 2) * 4, w0 = (tile & 3) * 8;

    unsigned long long acc[2][2];
    #pragma unroll
    for (int i = 0; i < 2; i++)
        #pragma unroll
        for (int j = 0; j < 2; j++) acc[i][j] = 0ull;

    float2 pw[9];
    float  pv[2];

    auto ld_w = [&](int cc) {
        const float2* src = (const float2*)g_wA + (size_t)cc*2304 + tid;
        #pragma unroll
        for (int k = 0; k < 9; k++) pw[k] = src[k*256];
    };
    auto ld_v = [&](int cc) {
        #pragma unroll
        for (int k = 0; k < 2; k++) {
            int e = tid + k*256;
            float v = 0.f;
            if (e < 480) {
                int a = (e >= 240);
                int i = e - a*240;
                int ci = i / 60; int rem = i % 60;
                int r = rem / 10, c = rem % 10;
                int gh = h0 - 1 + r, gw = w0 - 1 + c;
                if (gh >= 0 && gh < HH && gw >= 0 && gw < WW) {
                    size_t gi = ((size_t)(b*CC + cc*4+ci)*HH + gh)*WW + gw;
                    v = a ? g_za[gi] : g_ubar[gi];
                }
            }
            pv[k] = v;
        }
    };

    ld_w(0); ld_v(0);

    for (int cc = 0; cc < 16; cc++) {
        {
            float2* wd = (float2*)s_wv + tid;
            #pragma unroll
            for (int k = 0; k < 9; k++) wd[k*256] = pw[k];
            #pragma unroll
            for (int k = 0; k < 2; k++) {
                int e = tid + k*256;
                if (e < 480) {
                    if (e >= 240) s_zav[e-240] = pv[k];
                    else          s_ubv[e]     = pv[k];
                }
            }
        }
        __syncthreads();
        if (cc < 15) { ld_w(cc+1); ld_v(cc+1); }

        #pragma unroll 2
        for (int ci = 0; ci < 4; ci++) {
            // sliding 2-row cache over tile rows pr0+kh, pr0+kh+1 (tile has 6 rows)
            unsigned long long ua[4], ub[4], za[4], zb[4];
            #pragma unroll
            for (int c = 0; c < 4; c++) {
                ua[c] = pk2(s_ubv[ci*60 + (pr0  )*10 + pc0 + c]);
                za[c] = pk2(s_zav[ci*60 + (pr0  )*10 + pc0 + c]);
                ub[c] = pk2(s_ubv[ci*60 + (pr0+1)*10 + pc0 + c]);
                zb[c] = pk2(s_zav[ci*60 + (pr0+1)*10 + pc0 + c]);
            }
            #pragma unroll
            for (int kh = 0; kh < 3; kh++) {
                ulonglong2 wv[3];
                #pragma unroll
                for (int kw = 0; kw < 3; kw++)
                    wv[kw] = *(const ulonglong2*)(s_wv + ((ci*9 + kh*3+kw)*32 + pairI)*4);
                #pragma unroll
                for (int kw = 0; kw < 3; kw++)
                    #pragma unroll
                    for (int px = 0; px < 2; px++) {
                        acc[0][px] = fma2(wv[kw].x, ua[px+kw], acc[0][px]);
                        acc[0][px] = fma2(wv[kw].y, za[px+kw], acc[0][px]);
                        acc[1][px] = fma2(wv[kw].x, ub[px+kw], acc[1][px]);
                        acc[1][px] = fma2(wv[kw].y, zb[px+kw], acc[1][px]);
                    }
                if (kh < 2) {
                    #pragma unroll
                    for (int c = 0; c < 4; c++) {
                        ua[c] = ub[c]; za[c] = zb[c];
                        ub[c] = pk2(s_ubv[ci*60 + (pr0+kh+2)*10 + pc0 + c]);
                        zb[c] = pk2(s_zav[ci*60 + (pr0+kh+2)*10 + pc0 + c]);
                    }
                }
            }
        }
        __syncthreads();
    }

    int co0 = 2 * pairI;
    #pragma unroll
    for (int pr = 0; pr < 2; pr++)
        #pragma unroll
        for (int px = 0; px < 2; px++) {
            int h = h0 + pr0 + pr;
            int w = w0 + pc0 + px;
            float lo, hi;
            unpk2(acc[pr][px], lo, hi);
            outA[((b*CC + co0    )*HH + h)*WW + w] = fminf(fmaxf(lo, 0.f), 1.f);
            outA[((b*CC + co0 + 1)*HH + h)*WW + w] = fminf(fmaxf(hi, 0.f), 1.f);
        }
}

// ============================================================
// final B: b_out = clip(conv(a,W_down,s2) + conv(z_b,W_bb), 0, 1) on 16x16
// ============================================================
__global__ __launch_bounds__(256) void finalB_k(const float* __restrict__ aIn,
                                                float* __restrict__ outB)
{
    __shared__ __align__(16) float s_av[1156];     // [4ci][17][17]
    __shared__ __align__(16) float s_zv[400];      // [4ci][10][10]
    __shared__ __align__(16) float s_wv[4608];

    int tid = threadIdx.x;
    int cq = tid & 15;
    int pb = tid >> 4;
    int pr0 = (pb >> 2) * 2;
    int pc0 = (pb & 3) * 2;
    int tile = blockIdx.x;           // 0..3
    int b    = blockIdx.z;
    int h0 = (tile >> 1) * 8, w0 = (tile & 1) * 8;   // out coords

    unsigned long long accA[2][2], accB[2][2];
    #pragma unroll
    for (int i = 0; i < 2; i++)
        #pragma unroll
        for (int j = 0; j < 2; j++) { accA[i][j] = 0ull; accB[i][j] = 0ull; }

    float2 pw[9];
    float  pa[5];
    float  pz[2];

    auto ld_w = [&](int cc) {
        const float2* src = (const float2*)g_wB + (size_t)cc*2304 + tid;
        #pragma unroll
        for (int k = 0; k < 9; k++) pw[k] = src[k*256];
    };
    auto ld_a = [&](int cc) {
        #pragma unroll
        for (int k = 0; k < 5; k++) {
            int e = tid + k*256;
            float v = 0.f;
            if (e < 1156) {
                int ci = e / 289; int i = e % 289;
                int r = i / 17, c = i % 17;
                int gh = 2*h0 + r, gw = 2*w0 + c;
                if (gh < HH && gw < WW)
                    v = aIn[((size_t)(b*CC + cc*4+ci)*HH + gh)*WW + gw];
            }
            pa[k] = v;
        }
    };
    auto ld_z = [&](int cc) {
        #pragma unroll
        for (int k = 0; k < 2; k++) {
            int e = tid + k*256;
            float v = 0.f;
            if (e < 400) {
                int ci = e / 100; int i = e % 100;
                int r = i / 10, c = i % 10;
                int gh = h0 - 1 + r, gw = w0 - 1 + c;
                if (gh >= 0 && gh < HO && gw >= 0 && gw < WO)
                    v = g_zb[((size_t)(b*CC + cc*4+ci)*HO + gh)*WO + gw];
            }
            pz[k] = v;
        }
    };

    ld_w(0); ld_a(0); ld_z(0);

    for (int cc = 0; cc < 16; cc++) {
        {
            float2* wd = (float2*)s_wv + tid;
            #pragma unroll
            for (int k = 0; k < 9; k++) wd[k*256] = pw[k];
            #pragma unroll
            for (int k = 0; k < 5; k++) {
                int e = tid + k*256;
                if (e < 1156) s_av[e] = pa[k];
            }
            #pragma unroll
            for (int k = 0; k < 2; k++) {
                int e = tid + k*256;
                if (e < 400) s_zv[e] = pz[k];
            }
        }
        __syncthreads();
        if (cc < 15) { ld_w(cc+1); ld_a(cc+1); ld_z(cc+1); }

        #pragma unroll 2
        for (int ci = 0; ci < 4; ci++) {
            #pragma unroll
            for (int kh = 0; kh < 3; kh++) {
                ulonglong2 wa[3], wb[3];
                #pragma unroll
                for (int kw = 0; kw < 3; kw++) {
                    const float* wp = s_wv + ((ci*9 + kh*3+kw)*32 + 2*cq)*4;
                    wa[kw] = *(const ulonglong2*)wp;
                    wb[kw] = *(const ulonglong2*)(wp + 4);
                }
                #pragma unroll
                for (int pr = 0; pr < 2; pr++) {
                    int ra = 2*(pr0 + pr) + kh;      // 0..16
                    int rz = pr0 + pr + kh;          // 0..9
                    unsigned long long va[5], vz[4];
                    #pragma unroll
                    for (int c = 0; c < 5; c++)
                        va[c] = pk2(s_av[ci*289 + ra*17 + 2*pc0 + c]);
                    #pragma unroll
                    for (int c = 0; c < 4; c++)
                        vz[c] = pk2(s_zv[ci*100 + rz*10 + pc0 + c]);
                    #pragma unroll
                    for (int kw = 0; kw < 3; kw++)
                        #pragma unroll
                        for (int px = 0; px < 2; px++) {
                            accA[pr][px] = fma2(wa[kw].x, va[2*px+kw], accA[pr][px]);
                            accA[pr][px] = fma2(wa[kw].y, vz[px+kw],   accA[pr][px]);
                            accB[pr][px] = fma2(wb[kw].x, va[2*px+kw], accB[pr][px]);
                            accB[pr][px] = fma2(wb[kw].y, vz[px+kw],   accB[pr][px]);
                        }
                }
            }
        }
        __syncthreads();
    }

    int co0 = 4 * cq;
    #pragma unroll
    for (int pr = 0; pr < 2; pr++)
        #pragma unroll
        for (int px = 0; px < 2; px++) {
            int h = h0 + pr0 + pr;
            int w = w0 + pc0 + px;
            float lo, hi;
            unpk2(accA[pr][px], lo, hi);
            outB[((b*CC + co0    )*HO + h)*WO + w] = fminf(fmaxf(lo, 0.f), 1.f);
            outB[((b*CC + co0 + 1)*HO + h)*WO + w] = fminf(fmaxf(hi, 0.f), 1.f);
            unpk2(accB[pr][px], lo, hi);
            outB[((b*CC + co0 + 2)*HO + h)*WO + w] = fminf(fmaxf(lo, 0.f), 1.f);
            outB[((b*CC + co0 + 3)*HO + h)*WO + w] = fminf(fmaxf(hi, 0.f), 1.f);
        }
}

// ============================================================
extern "C" void kernel_launch(void* const* d_in, const int* in_sizes, int n_in,
                              void* d_out, int out_size)
{
    (void)in_sizes; (void)n_in; (void)out_size;
    const float* u   = (const float*)d_in[0];
    const float* Win = (const float*)d_in[1];
    const float* Waa = (const float*)d_in[2];
    const float* Wdn = (const float*)d_in[3];
    const float* Wbb = (const float*)d_in[4];
    float* outA = (float*)d_out;                      // a: [16,64,32,32]
    float* outB = outA + BB*CC*HH*WW;                 // b: [16,64,16,16]

    cudaFuncSetAttribute(conv1_k, cudaFuncAttributeMaxDynamicSharedMemorySize, 67584);
    cudaFuncSetAttribute(conv2_k, cudaFuncAttributeMaxDynamicSharedMemorySize, 55296);

    wprep_k<<<864, 256>>>(Win, Waa, Wdn, Wbb);
    ubar_k <<<(BB*CC*HH*WW + 255)/256, 256>>>(u);
    conv1_k<<<dim3(128, 2, BB), 256, 67584>>>(u);
    conv2_k<<<dim3(32, 2, BB), 256, 55296>>>();
    finalA_k<<<dim3(32, 1, BB), 256>>>(outA);
    finalB_k<<<dim3(4, 1, BB), 256>>>(outA, outB);
}